// round 1
// baseline (speedup 1.0000x reference)
#include <cuda_runtime.h>
#include <math.h>

// Problem constants (fixed by the reference)
#define M_TOK   32768      // B*S = 8*4096
#define NDIM    512        // E = O = 512
#define DT_C    0.01f
#define NSTEPS  10

// Scratch (allocation-free rule: __device__ globals)
__device__ float g_buf1[M_TOK * NDIM];
__device__ float g_buf2[M_TOK * NDIM];

// ---------------------------------------------------------------------------
// SGEMM: C[M,N] = act(A[M,K] @ B[K,N] + bias[N]); M=32768, N=K=512.
// BM=BN=128, BK=16, 256 threads, 8x8 register tile per thread.
// EPI: 0 = identity, 1 = tanh, 2 = relu,
//      3 = write [.,.,4] output: {v, im, im, im}, im = noise*sin(alpha*n)
// ---------------------------------------------------------------------------
template<int EPI>
__global__ __launch_bounds__(256)
void sgemm_kernel(const float* __restrict__ A, const float* __restrict__ B,
                  const float* __restrict__ bias, float* __restrict__ C,
                  const float* __restrict__ noise, const float* __restrict__ alpha_p)
{
    __shared__ __align__(16) float As[16][128];
    __shared__ __align__(16) float Bs[16][128];

    const int tid = threadIdx.x;
    const int m0  = blockIdx.y * 128;
    const int n0  = blockIdx.x * 128;

    const int tx   = tid & 15;
    const int ty   = tid >> 4;
    const int row0 = ty * 8;   // within tile
    const int col0 = tx * 8;

    float acc[8][8];
#pragma unroll
    for (int i = 0; i < 8; i++)
#pragma unroll
        for (int j = 0; j < 8; j++) acc[i][j] = 0.f;

    for (int k0 = 0; k0 < NDIM; k0 += 16) {
        // Load A tile (128x16) transposed into As[16][128]; B tile (16x128) direct.
#pragma unroll
        for (int u = 0; u < 2; u++) {
            const int f  = tid * 2 + u;          // float4 index 0..511
            const int ar = f >> 2;               // A tile row (0..127)
            const int ac = (f & 3) * 4;          // A tile col (0..12)
            float4 av = *(const float4*)(A + (size_t)(m0 + ar) * NDIM + k0 + ac);
            As[ac + 0][ar] = av.x;
            As[ac + 1][ar] = av.y;
            As[ac + 2][ar] = av.z;
            As[ac + 3][ar] = av.w;

            const int br = f >> 5;               // B tile row (0..15)
            const int bc = (f & 31) * 4;         // B tile col (0..124)
            *(float4*)&Bs[br][bc] =
                *(const float4*)(B + (size_t)(k0 + br) * NDIM + n0 + bc);
        }
        __syncthreads();

#pragma unroll
        for (int kk = 0; kk < 16; kk++) {
            float a[8], b[8];
            *(float4*)(a + 0) = *(const float4*)&As[kk][row0 + 0];
            *(float4*)(a + 4) = *(const float4*)&As[kk][row0 + 4];
            *(float4*)(b + 0) = *(const float4*)&Bs[kk][col0 + 0];
            *(float4*)(b + 4) = *(const float4*)&Bs[kk][col0 + 4];
#pragma unroll
            for (int i = 0; i < 8; i++)
#pragma unroll
                for (int j = 0; j < 8; j++)
                    acc[i][j] = fmaf(a[i], b[j], acc[i][j]);
        }
        __syncthreads();
    }

    // Bias for this thread's 8 columns
    float bb[8];
    *(float4*)(bb + 0) = *(const float4*)(bias + n0 + col0 + 0);
    *(float4*)(bb + 4) = *(const float4*)(bias + n0 + col0 + 4);

    if (EPI == 3) {
        const float alpha = *alpha_p;
        float fm[8];
#pragma unroll
        for (int j = 0; j < 8; j++)
            fm[j] = sinf(alpha * (float)(n0 + col0 + j));

#pragma unroll
        for (int i = 0; i < 8; i++) {
            const size_t m    = (size_t)(m0 + row0 + i);
            const size_t base = m * NDIM + (n0 + col0);
            float nz[8];
            *(float4*)(nz + 0) = *(const float4*)(noise + base + 0);
            *(float4*)(nz + 4) = *(const float4*)(noise + base + 4);
#pragma unroll
            for (int j = 0; j < 8; j++) {
                const float v  = acc[i][j] + bb[j];
                const float im = nz[j] * fm[j];
                float4 o = make_float4(v, im, im, im);
                *(float4*)(C + (base + j) * 4) = o;
            }
        }
    } else {
#pragma unroll
        for (int i = 0; i < 8; i++) {
            const size_t base = (size_t)(m0 + row0 + i) * NDIM + (n0 + col0);
#pragma unroll
            for (int p = 0; p < 2; p++) {
                float4 v;
                float r0 = acc[i][p * 4 + 0] + bb[p * 4 + 0];
                float r1 = acc[i][p * 4 + 1] + bb[p * 4 + 1];
                float r2 = acc[i][p * 4 + 2] + bb[p * 4 + 2];
                float r3 = acc[i][p * 4 + 3] + bb[p * 4 + 3];
                if (EPI == 1) {
                    r0 = tanhf(r0); r1 = tanhf(r1); r2 = tanhf(r2); r3 = tanhf(r3);
                } else if (EPI == 2) {
                    r0 = fmaxf(r0, 0.f); r1 = fmaxf(r1, 0.f);
                    r2 = fmaxf(r2, 0.f); r3 = fmaxf(r3, 0.f);
                }
                v = make_float4(r0, r1, r2, r3);
                *(float4*)(C + base + p * 4) = v;
            }
        }
    }
}

// ---------------------------------------------------------------------------
// Kuramoto recurrence, 10 steps, in place on P[M_TOK, 512].
// One warp per token; each lane owns 16 phases (lane + 32*i).
// Maintain (sin, cos) by small-angle rotation: |d| <= ~0.015, so
// cd = 1 - d^2/2, sd = d gives per-step error ~d^3/6 ~ 6e-10.
// ---------------------------------------------------------------------------
__global__ __launch_bounds__(256)
void kuramoto_kernel(float* __restrict__ P, const float* __restrict__ omega,
                     const float* __restrict__ Kp)
{
    const int gwarp = (blockIdx.x * blockDim.x + threadIdx.x) >> 5;  // token
    const int lane  = threadIdx.x & 31;
    if (gwarp >= M_TOK) return;

    float* ph = P + (size_t)gwarp * NDIM;
    const float Kv = *Kp;
    const float a_scale = DT_C * Kv * (1.0f / (float)NDIM);

    float p[16], s[16], c[16], w[16];
#pragma unroll
    for (int i = 0; i < 16; i++) {
        const int e = lane + 32 * i;
        p[i] = ph[e];
        w[i] = DT_C * omega[e];
        sincosf(p[i], &s[i], &c[i]);
    }

#pragma unroll 1
    for (int step = 0; step < NSTEPS; step++) {
        float part = 0.f;
#pragma unroll
        for (int i = 0; i < 16; i++) part += s[i];
#pragma unroll
        for (int off = 16; off > 0; off >>= 1)
            part += __shfl_xor_sync(0xFFFFFFFFu, part, off);
        const float a = a_scale * part;   // DT * K * mean(sin)

#pragma unroll
        for (int i = 0; i < 16; i++) {
            const float d  = fmaf(a, c[i], w[i]);   // DT*(omega + K*m*cos)
            p[i] += d;
            const float cd = fmaf(-0.5f * d, d, 1.0f);
            const float sn = fmaf(c[i],  d, s[i] * cd);
            const float cn = fmaf(-s[i], d, c[i] * cd);
            s[i] = sn;
            c[i] = cn;
        }
    }

#pragma unroll
    for (int i = 0; i < 16; i++) ph[lane + 32 * i] = p[i];
}

// ---------------------------------------------------------------------------
extern "C" void kernel_launch(void* const* d_in, const int* in_sizes, int n_in,
                              void* d_out, int out_size)
{
    const float* x      = (const float*)d_in[0];
    const float* W1     = (const float*)d_in[1];
    const float* b1     = (const float*)d_in[2];
    const float* W2     = (const float*)d_in[3];
    const float* b2     = (const float*)d_in[4];
    const float* omega  = (const float*)d_in[5];
    const float* Kp     = (const float*)d_in[6];
    const float* alphap = (const float*)d_in[7];
    const float* F1     = (const float*)d_in[8];
    const float* c1     = (const float*)d_in[9];
    const float* F2     = (const float*)d_in[10];
    const float* c2     = (const float*)d_in[11];
    const float* noise  = (const float*)d_in[12];
    float* out = (float*)d_out;

    float *buf1, *buf2;
    cudaGetSymbolAddress((void**)&buf1, g_buf1);
    cudaGetSymbolAddress((void**)&buf2, g_buf2);

    dim3 grid(NDIM / 128, M_TOK / 128);   // (4, 256)
    dim3 blk(256);

    // phases = tanh(x @ W1 + b1)
    sgemm_kernel<1><<<grid, blk>>>(x, W1, b1, buf1, nullptr, nullptr);
    // phases = phases @ W2 + b2
    sgemm_kernel<0><<<grid, blk>>>(buf1, W2, b2, buf2, nullptr, nullptr);
    // 10-step Kuramoto (in place)
    kuramoto_kernel<<<M_TOK / 8, 256>>>(buf2, omega, Kp);
    // h = relu(phases @ F1 + c1)
    sgemm_kernel<2><<<grid, blk>>>(buf2, F1, c1, buf1, nullptr, nullptr);
    // consciousness = h @ F2 + c2, fused with output expansion (noise channels)
    sgemm_kernel<3><<<grid, blk>>>(buf1, F2, c2, out, noise, alphap);
}

// round 3
// speedup vs baseline: 1.9876x; 1.9876x over previous
#include <cuda_runtime.h>
#include <cuda_bf16.h>
#include <cstdint>
#include <math.h>

// ---------------------------------------------------------------------------
// Problem constants
// ---------------------------------------------------------------------------
#define M_TOK 32768      // B*S
#define NDIM  512        // E = O
#define DT_C  0.01f
#define NSTEPS 10

// GEMM tiling
#define BM 128
#define BN 128
#define BK 32
#define NCHUNK 16        // 512 / 32

// smem: each tile 128 rows x 80B (64B data + 16B pad -> conflict-free ldmatrix)
#define ROWB 80
#define TILE_B (128 * ROWB)          // 10240
#define OFF_AH 0
#define OFF_AL (1 * TILE_B)
#define OFF_BH (2 * TILE_B)
#define OFF_BL (3 * TILE_B)
#define STAGE_BYTES (4 * TILE_B)     // 40960
#define NSTAGE 3
#define SM_CTRL 2048
#define GEMM_SMEM (SM_CTRL + NSTAGE * STAGE_BYTES)   // 124928

// ---------------------------------------------------------------------------
// Global scratch (allocation-free rule)
// ---------------------------------------------------------------------------
__device__ __nv_bfloat16 g_a_hi[M_TOK*NDIM];
__device__ __nv_bfloat16 g_a_lo[M_TOK*NDIM];
__device__ __nv_bfloat16 g_b_hi[M_TOK*NDIM];
__device__ __nv_bfloat16 g_b_lo[M_TOK*NDIM];
__device__ float         g_ph[M_TOK*NDIM];
__device__ __nv_bfloat16 g_w_hi[4*NDIM*NDIM];
__device__ __nv_bfloat16 g_w_lo[4*NDIM*NDIM];

// ---------------------------------------------------------------------------
// PTX helpers (sm_80-era only: cp.async, ldmatrix, mma.sync)
// ---------------------------------------------------------------------------
static __device__ __forceinline__ uint32_t smem_u32(const void* p) {
    uint32_t a;
    asm("{ .reg .u64 t; cvta.to.shared.u64 t, %1; cvt.u32.u64 %0, t; }" : "=r"(a) : "l"(p));
    return a;
}
static __device__ __forceinline__ void cp16(uint32_t dst, const void* src) {
    asm volatile("cp.async.cg.shared.global [%0], [%1], 16;" :: "r"(dst), "l"(src));
}
#define CP_COMMIT() asm volatile("cp.async.commit_group;" ::: "memory")
#define CP_WAIT(n)  asm volatile("cp.async.wait_group %0;" :: "n"(n) : "memory")

#define LDSM4(r, addr) \
    asm volatile("ldmatrix.sync.aligned.m8n8.x4.shared.b16 {%0,%1,%2,%3}, [%4];" \
        : "=r"((r)[0]), "=r"((r)[1]), "=r"((r)[2]), "=r"((r)[3]) : "r"(addr))

static __device__ __forceinline__ void mma16816(float* c, const uint32_t* a,
                                                const uint32_t b0, const uint32_t b1) {
    asm volatile("mma.sync.aligned.m16n8k16.row.col.f32.bf16.bf16.f32 "
        "{%0,%1,%2,%3}, {%4,%5,%6,%7}, {%8,%9}, {%0,%1,%2,%3};"
        : "+f"(c[0]), "+f"(c[1]), "+f"(c[2]), "+f"(c[3])
        : "r"(a[0]), "r"(a[1]), "r"(a[2]), "r"(a[3]), "r"(b0), "r"(b1));
}

// ---------------------------------------------------------------------------
// Load one K-chunk (A,B: 128 rows x 32 cols bf16, hi+lo each) into a stage
// ---------------------------------------------------------------------------
static __device__ __forceinline__ void load_chunk(
    uint32_t stage,
    const __nv_bfloat16* __restrict__ Ah, const __nv_bfloat16* __restrict__ Al,
    const __nv_bfloat16* __restrict__ Bh, const __nv_bfloat16* __restrict__ Bl,
    int m0, int n0, int kc0, int tid)
{
#pragma unroll
    for (int i = 0; i < 2; i++) {
        const int t   = tid + i * 256;       // 0..511
        const int row = t >> 2;              // 0..127
        const int q   = t & 3;               // 16B chunk within 64B row
        const uint32_t so = (uint32_t)(row * ROWB + q * 16);
        const size_t ga = (size_t)(m0 + row) * NDIM + kc0 + q * 8;
        const size_t gb = (size_t)(n0 + row) * NDIM + kc0 + q * 8;
        cp16(stage + OFF_AH + so, Ah + ga);
        cp16(stage + OFF_AL + so, Al + ga);
        cp16(stage + OFF_BH + so, Bh + gb);
        cp16(stage + OFF_BL + so, Bl + gb);
    }
    CP_COMMIT();
}

// ---------------------------------------------------------------------------
// bf16x3 GEMM: C[M,N] = act(A @ B^T + bias); A=[M,512] hi/lo, B=[N,512] hi/lo
// EPI: 0 -> fp32 to outF; 1 -> tanh to hi/lo; 2 -> relu to hi/lo;
//      3 -> final [m,n,4] output {v, im, im, im},  im = noise*sin(alpha*n)
// ---------------------------------------------------------------------------
template<int EPI>
__global__ void __launch_bounds__(256, 1)
gemm_bf16x3(const __nv_bfloat16* __restrict__ Ah, const __nv_bfloat16* __restrict__ Al,
            const __nv_bfloat16* __restrict__ Bh, const __nv_bfloat16* __restrict__ Bl,
            const float* __restrict__ bias,
            __nv_bfloat16* __restrict__ outHi, __nv_bfloat16* __restrict__ outLo,
            float* __restrict__ outF,
            const float* __restrict__ noise, const float* __restrict__ alpha_p)
{
    extern __shared__ char smem[];
    const uint32_t sb = smem_u32(smem);
    const int tid  = threadIdx.x;
    const int wid  = tid >> 5;
    const int lane = tid & 31;
    const int m0 = blockIdx.y * BM;
    const int n0 = blockIdx.x * BN;

    const int wm = wid & 3;        // 4 warps along M (32 rows each)
    const int wn = wid >> 2;       // 2 warps along N (64 cols each)

    // ctrl region: fm cache (EPI3) at +64, bias at +1088
    float* fm_s   = (float*)(smem + 64);
    float* bias_s = (float*)(smem + 1088);
    if (tid < 128) {
        bias_s[tid] = bias[n0 + tid];
        if (EPI == 3) fm_s[tid] = sinf((*alpha_p) * (float)(n0 + tid));
    }

    // prologue loads
    load_chunk(sb + SM_CTRL,               Ah, Al, Bh, Bl, m0, n0, 0,      tid);
    load_chunk(sb + SM_CTRL + STAGE_BYTES, Ah, Al, Bh, Bl, m0, n0, BK,     tid);

    // per-thread ldmatrix base offsets (within a tile)
    const int g  = lane >> 3;
    const int lr = lane & 7;
    // A: matrices [m0-7 k0-7][m8-15 k0-7][m0-7 k8-15][m8-15 k8-15]
    const uint32_t offA = (uint32_t)((wm * 32 + (g & 1) * 8 + lr) * ROWB + (g >> 1) * 16);
    // B: matrices [n0-7 k0-7][n0-7 k8-15][n8-15 k0-7][n8-15 k8-15]
    const uint32_t offB = (uint32_t)((wn * 64 + (g >> 1) * 8 + lr) * ROWB + (g & 1) * 16);

    float acc[2][8][4];
#pragma unroll
    for (int mt = 0; mt < 2; mt++)
#pragma unroll
        for (int nt = 0; nt < 8; nt++)
#pragma unroll
            for (int r = 0; r < 4; r++) acc[mt][nt][r] = 0.f;

#pragma unroll 1
    for (int c = 0; c < NCHUNK; c++) {
        if (c == NCHUNK - 1) { CP_WAIT(0); } else { CP_WAIT(1); }
        __syncthreads();

        const uint32_t stage = sb + SM_CTRL + (c % NSTAGE) * STAGE_BYTES;
#pragma unroll
        for (int ks = 0; ks < 2; ks++) {
            uint32_t ah[2][4], al[2][4], bh[4][4], bl[4][4];
#pragma unroll
            for (int mt = 0; mt < 2; mt++) {
                const uint32_t a = stage + offA + mt * (16 * ROWB) + ks * 32;
                LDSM4(ah[mt], a + OFF_AH);
                LDSM4(al[mt], a + OFF_AL);
            }
#pragma unroll
            for (int bt = 0; bt < 4; bt++) {
                const uint32_t b = stage + offB + bt * (16 * ROWB) + ks * 32;
                LDSM4(bh[bt], b + OFF_BH);
                LDSM4(bl[bt], b + OFF_BL);
            }
#pragma unroll
            for (int mt = 0; mt < 2; mt++)
#pragma unroll
                for (int nt = 0; nt < 8; nt++) {
                    const int bt = nt >> 1, sel = (nt & 1) * 2;
                    mma16816(acc[mt][nt], ah[mt], bh[bt][sel], bh[bt][sel + 1]);
                    mma16816(acc[mt][nt], ah[mt], bl[bt][sel], bl[bt][sel + 1]);
                    mma16816(acc[mt][nt], al[mt], bh[bt][sel], bh[bt][sel + 1]);
                }
        }
        __syncthreads();

        if (c + 2 < NCHUNK)
            load_chunk(sb + SM_CTRL + ((c + 2) % NSTAGE) * STAGE_BYTES,
                       Ah, Al, Bh, Bl, m0, n0, (c + 2) * BK, tid);
    }

    // ------------------------- epilogue -------------------------
    const int rbase = wm * 32 + (lane >> 2);
    const int cbase = wn * 64 + (lane & 3) * 2;

    if (EPI == 1 || EPI == 2) {
        __nv_bfloat16* sHi = (__nv_bfloat16*)(smem + SM_CTRL);
        __nv_bfloat16* sLo = sHi + 128 * 136;
#pragma unroll
        for (int mt = 0; mt < 2; mt++)
#pragma unroll
            for (int nt = 0; nt < 8; nt++) {
                const int col = cbase + nt * 8;
#pragma unroll
                for (int h = 0; h < 2; h++) {
                    const int r = rbase + mt * 16 + h * 8;
#pragma unroll
                    for (int e = 0; e < 2; e++) {
                        float v = acc[mt][nt][h * 2 + e] + bias_s[col + e];
                        if (EPI == 1) v = tanhf(v);
                        else          v = fmaxf(v, 0.f);
                        const __nv_bfloat16 hh = __float2bfloat16(v);
                        sHi[r * 136 + col + e] = hh;
                        sLo[r * 136 + col + e] = __float2bfloat16(v - __bfloat162float(hh));
                    }
                }
            }
        __syncthreads();
#pragma unroll
        for (int i = 0; i < 8; i++) {
            const int t = tid + i * 256;          // 0..2047
            const int row = t >> 4, q = t & 15;   // 16 uint4 per 128-col row
            const size_t gb = ((size_t)(m0 + row) * NDIM + n0) * 2;
            *(uint4*)((char*)outHi + gb + q * 16) = *(uint4*)((char*)sHi + row * 272 + q * 16);
            *(uint4*)((char*)outLo + gb + q * 16) = *(uint4*)((char*)sLo + row * 272 + q * 16);
        }
    } else {
        float* sC = (float*)(smem + SM_CTRL);     // stride 132 floats
#pragma unroll
        for (int mt = 0; mt < 2; mt++)
#pragma unroll
            for (int nt = 0; nt < 8; nt++) {
                const int col = cbase + nt * 8;
#pragma unroll
                for (int h = 0; h < 2; h++) {
                    const int r = rbase + mt * 16 + h * 8;
                    sC[r * 132 + col + 0] = acc[mt][nt][h * 2 + 0] + bias_s[col + 0];
                    sC[r * 132 + col + 1] = acc[mt][nt][h * 2 + 1] + bias_s[col + 1];
                }
            }
        __syncthreads();
        if (EPI == 0) {
#pragma unroll
            for (int i = 0; i < 16; i++) {
                const int t = tid + i * 256;      // 0..4095
                const int row = t >> 5, q = t & 31;
                *(float4*)(outF + (size_t)(m0 + row) * NDIM + n0 + q * 4) =
                    *(float4*)((char*)sC + row * 528 + q * 16);
            }
        } else {   // EPI == 3
#pragma unroll 4
            for (int i = 0; i < 64; i++) {
                const int t = tid + i * 256;      // 0..16383
                const int row = t >> 7, n = t & 127;
                const float v  = sC[row * 132 + n];
                const size_t e = (size_t)(m0 + row) * NDIM + n0 + n;
                const float im = noise[e] * fm_s[n];
                *(float4*)(outF + e * 4) = make_float4(v, im, im, im);
            }
        }
    }
}

// ---------------------------------------------------------------------------
// fp32 -> bf16 hi/lo split (for x)
// ---------------------------------------------------------------------------
__global__ void __launch_bounds__(256)
conv_split(const float* __restrict__ x, __nv_bfloat16* __restrict__ hi,
           __nv_bfloat16* __restrict__ lo)
{
    const int n4 = M_TOK * NDIM / 4;
    for (int i = blockIdx.x * blockDim.x + threadIdx.x; i < n4; i += gridDim.x * blockDim.x) {
        const float4 v = *(const float4*)(x + i * 4);
        __nv_bfloat16 h0 = __float2bfloat16(v.x), h1 = __float2bfloat16(v.y);
        __nv_bfloat16 h2 = __float2bfloat16(v.z), h3 = __float2bfloat16(v.w);
        __nv_bfloat162* H = (__nv_bfloat162*)(hi + i * 4);
        __nv_bfloat162* L = (__nv_bfloat162*)(lo + i * 4);
        H[0] = __nv_bfloat162(h0, h1); H[1] = __nv_bfloat162(h2, h3);
        L[0] = __nv_bfloat162(__float2bfloat16(v.x - __bfloat162float(h0)),
                              __float2bfloat16(v.y - __bfloat162float(h1)));
        L[1] = __nv_bfloat162(__float2bfloat16(v.z - __bfloat162float(h2)),
                              __float2bfloat16(v.w - __bfloat162float(h3)));
    }
}

// ---------------------------------------------------------------------------
// Weight prep: Wt[n,k] = W[k,n], split to bf16 hi/lo
// ---------------------------------------------------------------------------
__global__ void __launch_bounds__(256)
wprep(const float* __restrict__ W, __nv_bfloat16* __restrict__ Th,
      __nv_bfloat16* __restrict__ Tl)
{
    __shared__ float tile[32][33];
    const int bx = blockIdx.x * 32, by = blockIdx.y * 32;
    const int tx = threadIdx.x & 31, ty = threadIdx.x >> 5;  // 32 x 8
#pragma unroll
    for (int r = 0; r < 32; r += 8)
        tile[ty + r][tx] = W[(size_t)(by + ty + r) * NDIM + bx + tx];
    __syncthreads();
#pragma unroll
    for (int r = 0; r < 32; r += 8) {
        const float w = tile[tx][ty + r];
        const __nv_bfloat16 h = __float2bfloat16(w);
        const size_t d = (size_t)(bx + ty + r) * NDIM + by + tx;
        Th[d] = h;
        Tl[d] = __float2bfloat16(w - __bfloat162float(h));
    }
}

// ---------------------------------------------------------------------------
// Kuramoto: 10 steps in place (rotation trick), emits bf16 hi/lo phases
// ---------------------------------------------------------------------------
__global__ void __launch_bounds__(256)
kuramoto_kernel(const float* __restrict__ P, const float* __restrict__ omega,
                const float* __restrict__ Kp,
                __nv_bfloat16* __restrict__ outHi, __nv_bfloat16* __restrict__ outLo)
{
    const int gwarp = (blockIdx.x * blockDim.x + threadIdx.x) >> 5;
    const int lane  = threadIdx.x & 31;
    if (gwarp >= M_TOK) return;

    const float* ph = P + (size_t)gwarp * NDIM;
    const float Kv = *Kp;
    const float a_scale = DT_C * Kv * (1.0f / (float)NDIM);

    float p[16], s[16], c[16], w[16];
#pragma unroll
    for (int i = 0; i < 16; i++) {
        const int e = lane + 32 * i;
        p[i] = ph[e];
        w[i] = DT_C * omega[e];
        sincosf(p[i], &s[i], &c[i]);
    }
#pragma unroll 1
    for (int step = 0; step < NSTEPS; step++) {
        float part = 0.f;
#pragma unroll
        for (int i = 0; i < 16; i++) part += s[i];
#pragma unroll
        for (int off = 16; off > 0; off >>= 1)
            part += __shfl_xor_sync(0xFFFFFFFFu, part, off);
        const float a = a_scale * part;
#pragma unroll
        for (int i = 0; i < 16; i++) {
            const float d  = fmaf(a, c[i], w[i]);
            p[i] += d;
            const float cd = fmaf(-0.5f * d, d, 1.0f);
            const float sn = fmaf(c[i],  d, s[i] * cd);
            const float cn = fmaf(-s[i], d, c[i] * cd);
            s[i] = sn; c[i] = cn;
        }
    }
    const size_t base = (size_t)gwarp * NDIM;
#pragma unroll
    for (int i = 0; i < 16; i++) {
        const size_t e = base + lane + 32 * i;
        const __nv_bfloat16 h = __float2bfloat16(p[i]);
        outHi[e] = h;
        outLo[e] = __float2bfloat16(p[i] - __bfloat162float(h));
    }
}

// ---------------------------------------------------------------------------
extern "C" void kernel_launch(void* const* d_in, const int* in_sizes, int n_in,
                              void* d_out, int out_size)
{
    const float* x      = (const float*)d_in[0];
    const float* W1     = (const float*)d_in[1];
    const float* b1     = (const float*)d_in[2];
    const float* W2     = (const float*)d_in[3];
    const float* b2     = (const float*)d_in[4];
    const float* omega  = (const float*)d_in[5];
    const float* Kp     = (const float*)d_in[6];
    const float* alphap = (const float*)d_in[7];
    const float* F1     = (const float*)d_in[8];
    const float* c1     = (const float*)d_in[9];
    const float* F2     = (const float*)d_in[10];
    const float* c2     = (const float*)d_in[11];
    const float* noise  = (const float*)d_in[12];
    float* out = (float*)d_out;

    __nv_bfloat16 *aHi, *aLo, *bHi, *bLo, *wHi, *wLo;
    float* phb;
    cudaGetSymbolAddress((void**)&aHi, g_a_hi);
    cudaGetSymbolAddress((void**)&aLo, g_a_lo);
    cudaGetSymbolAddress((void**)&bHi, g_b_hi);
    cudaGetSymbolAddress((void**)&bLo, g_b_lo);
    cudaGetSymbolAddress((void**)&wHi, g_w_hi);
    cudaGetSymbolAddress((void**)&wLo, g_w_lo);
    cudaGetSymbolAddress((void**)&phb, g_ph);

    cudaFuncSetAttribute(gemm_bf16x3<0>, cudaFuncAttributeMaxDynamicSharedMemorySize, GEMM_SMEM);
    cudaFuncSetAttribute(gemm_bf16x3<1>, cudaFuncAttributeMaxDynamicSharedMemorySize, GEMM_SMEM);
    cudaFuncSetAttribute(gemm_bf16x3<2>, cudaFuncAttributeMaxDynamicSharedMemorySize, GEMM_SMEM);
    cudaFuncSetAttribute(gemm_bf16x3<3>, cudaFuncAttributeMaxDynamicSharedMemorySize, GEMM_SMEM);

    const size_t WSZ = (size_t)NDIM * NDIM;
    dim3 wgrid(16, 16);
    wprep<<<wgrid, 256>>>(W1, wHi + 0*WSZ, wLo + 0*WSZ);
    wprep<<<wgrid, 256>>>(W2, wHi + 1*WSZ, wLo + 1*WSZ);
    wprep<<<wgrid, 256>>>(F1, wHi + 2*WSZ, wLo + 2*WSZ);
    wprep<<<wgrid, 256>>>(F2, wHi + 3*WSZ, wLo + 3*WSZ);
    conv_split<<<2048, 256>>>(x, aHi, aLo);

    dim3 ggrid(NDIM / BN, M_TOK / BM);   // (4, 256)

    // phases = tanh(x @ W1 + b1)
    gemm_bf16x3<1><<<ggrid, 256, GEMM_SMEM>>>(aHi, aLo, wHi + 0*WSZ, wLo + 0*WSZ,
                                              b1, bHi, bLo, nullptr, nullptr, nullptr);
    // phases = phases @ W2 + b2  (fp32 out)
    gemm_bf16x3<0><<<ggrid, 256, GEMM_SMEM>>>(bHi, bLo, wHi + 1*WSZ, wLo + 1*WSZ,
                                              b2, nullptr, nullptr, phb, nullptr, nullptr);
    // Kuramoto -> bf16 hi/lo phases
    kuramoto_kernel<<<M_TOK / 8, 256>>>(phb, omega, Kp, aHi, aLo);
    // h = relu(phases @ F1 + c1)
    gemm_bf16x3<2><<<ggrid, 256, GEMM_SMEM>>>(aHi, aLo, wHi + 2*WSZ, wLo + 2*WSZ,
                                              c1, bHi, bLo, nullptr, nullptr, nullptr);
    // out = expand(h @ F2 + c2, noise)
    gemm_bf16x3<3><<<ggrid, 256, GEMM_SMEM>>>(bHi, bLo, wHi + 3*WSZ, wLo + 3*WSZ,
                                              c2, nullptr, nullptr, out, noise, alphap);
}

// round 4
// speedup vs baseline: 2.5500x; 1.2830x over previous
#include <cuda_runtime.h>
#include <cuda_fp16.h>
#include <cstdint>
#include <math.h>

// ---------------------------------------------------------------------------
#define M_TOK 32768      // B*S
#define NDIM  512        // E = O
#define DT_C  0.01f
#define NSTEPS 10

#define BM 128
#define BN 128
#define BK 32
#define NCHUNK 16        // 512/32

// smem: tiles 128 rows x 80B (64B data + 16B pad -> conflict-free ldmatrix)
#define ROWB 80
#define TILE_B (128 * ROWB)          // 10240
#define OFF_A  0
#define OFF_BH (1 * TILE_B)
#define OFF_BL (2 * TILE_B)
#define STAGE_BYTES (3 * TILE_B)     // 30720
#define NSTAGE 4
#define SM_CTRL 2048
#define GEMM_SMEM (SM_CTRL + NSTAGE * STAGE_BYTES)   // 124928

// ---------------------------------------------------------------------------
// Global scratch (allocation-free rule)
// ---------------------------------------------------------------------------
__device__ __half g_act_a[M_TOK*NDIM];   // activations ping
__device__ __half g_act_b[M_TOK*NDIM];   // activations pong
__device__ float  g_ph[M_TOK*NDIM];      // fp32 phases for Kuramoto
__device__ __half g_w_hi[4*NDIM*NDIM];
__device__ __half g_w_lo[4*NDIM*NDIM];

// ---------------------------------------------------------------------------
// PTX helpers (sm_80-era only)
// ---------------------------------------------------------------------------
static __device__ __forceinline__ uint32_t smem_u32(const void* p) {
    uint32_t a;
    asm("{ .reg .u64 t; cvta.to.shared.u64 t, %1; cvt.u32.u64 %0, t; }" : "=r"(a) : "l"(p));
    return a;
}
static __device__ __forceinline__ void cp16(uint32_t dst, const void* src) {
    asm volatile("cp.async.cg.shared.global [%0], [%1], 16;" :: "r"(dst), "l"(src));
}
#define CP_COMMIT() asm volatile("cp.async.commit_group;" ::: "memory")
#define CP_WAIT(n)  asm volatile("cp.async.wait_group %0;" :: "n"(n) : "memory")

#define LDSM4(r, addr) \
    asm volatile("ldmatrix.sync.aligned.m8n8.x4.shared.b16 {%0,%1,%2,%3}, [%4];" \
        : "=r"((r)[0]), "=r"((r)[1]), "=r"((r)[2]), "=r"((r)[3]) : "r"(addr))

static __device__ __forceinline__ void mma16816(float* c, const uint32_t* a,
                                                const uint32_t b0, const uint32_t b1) {
    asm volatile("mma.sync.aligned.m16n8k16.row.col.f32.f16.f16.f32 "
        "{%0,%1,%2,%3}, {%4,%5,%6,%7}, {%8,%9}, {%0,%1,%2,%3};"
        : "+f"(c[0]), "+f"(c[1]), "+f"(c[2]), "+f"(c[3])
        : "r"(a[0]), "r"(a[1]), "r"(a[2]), "r"(a[3]), "r"(b0), "r"(b1));
}

// ---------------------------------------------------------------------------
// Load one K-chunk: A (128x32 fp16) + Bh + Bl into a stage. 6 cp16/thread.
// ---------------------------------------------------------------------------
static __device__ __forceinline__ void load_chunk(
    uint32_t stage,
    const __half* __restrict__ A,
    const __half* __restrict__ Bh, const __half* __restrict__ Bl,
    int m0, int n0, int kc0, int tid)
{
#pragma unroll
    for (int i = 0; i < 2; i++) {
        const int t   = tid + i * 256;       // 0..511
        const int row = t >> 2;              // 0..127
        const int q   = t & 3;               // 16B chunk within 64B row
        const uint32_t so = (uint32_t)(row * ROWB + q * 16);
        const size_t ga = (size_t)(m0 + row) * NDIM + kc0 + q * 8;
        const size_t gb = (size_t)(n0 + row) * NDIM + kc0 + q * 8;
        cp16(stage + OFF_A  + so, A  + ga);
        cp16(stage + OFF_BH + so, Bh + gb);
        cp16(stage + OFF_BL + so, Bl + gb);
    }
    CP_COMMIT();
}

// ---------------------------------------------------------------------------
// fp16 2-term GEMM: C[M,N] = act(A @ (Bh+Bl)^T + bias)
// EPI: 0 -> fp32 outF; 1 -> tanh fp16 outH; 2 -> relu fp16 outH;
//      3 -> final [m,n,4] {v, im, im, im}, im = noise*sin(alpha*n)
// ---------------------------------------------------------------------------
template<int EPI>
__global__ void __launch_bounds__(256, 1)
gemm_f16x2(const __half* __restrict__ A,
           const __half* __restrict__ Bh, const __half* __restrict__ Bl,
           const float* __restrict__ bias,
           __half* __restrict__ outH, float* __restrict__ outF,
           const float* __restrict__ noise, const float* __restrict__ alpha_p)
{
    extern __shared__ char smem[];
    const uint32_t sb = smem_u32(smem);
    const int tid  = threadIdx.x;
    const int wid  = tid >> 5;
    const int lane = tid & 31;
    const int m0 = blockIdx.y * BM;
    const int n0 = blockIdx.x * BN;

    const int wm = wid & 3;        // 4 warps along M (32 rows)
    const int wn = wid >> 2;       // 2 warps along N (64 cols)

    float* fm_s   = (float*)(smem + 64);
    float* bias_s = (float*)(smem + 1088);
    if (tid < 128) {
        bias_s[tid] = bias[n0 + tid];
        if (EPI == 3) fm_s[tid] = sinf((*alpha_p) * (float)(n0 + tid));
    }

    // prologue: 3 stages
    load_chunk(sb + SM_CTRL + 0 * STAGE_BYTES, A, Bh, Bl, m0, n0, 0 * BK, tid);
    load_chunk(sb + SM_CTRL + 1 * STAGE_BYTES, A, Bh, Bl, m0, n0, 1 * BK, tid);
    load_chunk(sb + SM_CTRL + 2 * STAGE_BYTES, A, Bh, Bl, m0, n0, 2 * BK, tid);

    const int g  = lane >> 3;
    const int lr = lane & 7;
    const uint32_t offA = (uint32_t)((wm * 32 + (g & 1) * 8 + lr) * ROWB + (g >> 1) * 16);
    const uint32_t offB = (uint32_t)((wn * 64 + (g >> 1) * 8 + lr) * ROWB + (g & 1) * 16);

    float acc[2][8][4];
#pragma unroll
    for (int mt = 0; mt < 2; mt++)
#pragma unroll
        for (int nt = 0; nt < 8; nt++)
#pragma unroll
            for (int r = 0; r < 4; r++) acc[mt][nt][r] = 0.f;

#pragma unroll 1
    for (int c = 0; c < NCHUNK; c++) {
        CP_WAIT(2);                 // group c complete (3 groups always pending)
        __syncthreads();

        if (c + 3 < NCHUNK)
            load_chunk(sb + SM_CTRL + ((c + 3) & 3) * STAGE_BYTES,
                       A, Bh, Bl, m0, n0, (c + 3) * BK, tid);
        else
            CP_COMMIT();            // empty group keeps wait_group accounting exact

        const uint32_t stage = sb + SM_CTRL + (c & 3) * STAGE_BYTES;
#pragma unroll
        for (int ks = 0; ks < 2; ks++) {
            uint32_t a[2][4], bh[4][4], bl[4][4];
#pragma unroll
            for (int mt = 0; mt < 2; mt++)
                LDSM4(a[mt], stage + OFF_A + offA + mt * (16 * ROWB) + ks * 32);
#pragma unroll
            for (int bt = 0; bt < 4; bt++) {
                const uint32_t b = offB + bt * (16 * ROWB) + ks * 32;
                LDSM4(bh[bt], stage + OFF_BH + b);
                LDSM4(bl[bt], stage + OFF_BL + b);
            }
            // term 1: 16 independent MMAs (no accumulator RAW back-to-back)
#pragma unroll
            for (int mt = 0; mt < 2; mt++)
#pragma unroll
                for (int nt = 0; nt < 8; nt++) {
                    const int bt = nt >> 1, sel = (nt & 1) * 2;
                    mma16816(acc[mt][nt], a[mt], bh[bt][sel], bh[bt][sel + 1]);
                }
            // term 2
#pragma unroll
            for (int mt = 0; mt < 2; mt++)
#pragma unroll
                for (int nt = 0; nt < 8; nt++) {
                    const int bt = nt >> 1, sel = (nt & 1) * 2;
                    mma16816(acc[mt][nt], a[mt], bl[bt][sel], bl[bt][sel + 1]);
                }
        }
    }
    __syncthreads();   // protect stage smem before reuse by epilogue staging

    // ------------------------- epilogue -------------------------
    const int rbase = wm * 32 + (lane >> 2);
    const int cbase = wn * 64 + (lane & 3) * 2;

    if (EPI == 1 || EPI == 2) {
        __half* sH = (__half*)(smem + SM_CTRL);      // stride 136 halves (272B)
#pragma unroll
        for (int mt = 0; mt < 2; mt++)
#pragma unroll
            for (int nt = 0; nt < 8; nt++) {
                const int col = cbase + nt * 8;
#pragma unroll
                for (int h = 0; h < 2; h++) {
                    const int r = rbase + mt * 16 + h * 8;
                    float v0 = acc[mt][nt][h * 2 + 0] + bias_s[col + 0];
                    float v1 = acc[mt][nt][h * 2 + 1] + bias_s[col + 1];
                    if (EPI == 1) { v0 = tanhf(v0); v1 = tanhf(v1); }
                    else          { v0 = fmaxf(v0, 0.f); v1 = fmaxf(v1, 0.f); }
                    *(__half2*)&sH[r * 136 + col] = __floats2half2_rn(v0, v1);
                }
            }
        __syncthreads();
#pragma unroll
        for (int i = 0; i < 8; i++) {
            const int t = tid + i * 256;          // 0..2047
            const int row = t >> 4, q = t & 15;
            *(uint4*)((char*)outH + ((size_t)(m0 + row) * NDIM + n0) * 2 + q * 16) =
                *(uint4*)((char*)sH + row * 272 + q * 16);
        }
    } else {
        float* sC = (float*)(smem + SM_CTRL);     // stride 132 floats
#pragma unroll
        for (int mt = 0; mt < 2; mt++)
#pragma unroll
            for (int nt = 0; nt < 8; nt++) {
                const int col = cbase + nt * 8;
#pragma unroll
                for (int h = 0; h < 2; h++) {
                    const int r = rbase + mt * 16 + h * 8;
                    sC[r * 132 + col + 0] = acc[mt][nt][h * 2 + 0] + bias_s[col + 0];
                    sC[r * 132 + col + 1] = acc[mt][nt][h * 2 + 1] + bias_s[col + 1];
                }
            }
        __syncthreads();
        if (EPI == 0) {
#pragma unroll
            for (int i = 0; i < 16; i++) {
                const int t = tid + i * 256;      // 0..4095
                const int row = t >> 5, q = t & 31;
                *(float4*)(outF + (size_t)(m0 + row) * NDIM + n0 + q * 4) =
                    *(float4*)((char*)sC + row * 528 + q * 16);
            }
        } else {   // EPI == 3
#pragma unroll 4
            for (int i = 0; i < 64; i++) {
                const int t = tid + i * 256;      // 0..16383
                const int row = t >> 7, n = t & 127;
                const float v  = sC[row * 132 + n];
                const size_t e = (size_t)(m0 + row) * NDIM + n0 + n;
                const float im = noise[e] * fm_s[n];
                *(float4*)(outF + e * 4) = make_float4(v, im, im, im);
            }
        }
    }
}

// ---------------------------------------------------------------------------
// fp32 -> fp16 (for x)
// ---------------------------------------------------------------------------
__global__ void __launch_bounds__(256)
conv_f16(const float* __restrict__ x, __half* __restrict__ o)
{
    const int n4 = M_TOK * NDIM / 4;
    for (int i = blockIdx.x * blockDim.x + threadIdx.x; i < n4; i += gridDim.x * blockDim.x) {
        const float4 v = *(const float4*)(x + i * 4);
        __half2* O = (__half2*)(o + i * 4);
        O[0] = __floats2half2_rn(v.x, v.y);
        O[1] = __floats2half2_rn(v.z, v.w);
    }
}

// ---------------------------------------------------------------------------
// Weight prep: Wt[n,k] = W[k,n], split to fp16 hi/lo
// ---------------------------------------------------------------------------
__global__ void __launch_bounds__(256)
wprep(const float* __restrict__ W, __half* __restrict__ Th, __half* __restrict__ Tl)
{
    __shared__ float tile[32][33];
    const int bx = blockIdx.x * 32, by = blockIdx.y * 32;
    const int tx = threadIdx.x & 31, ty = threadIdx.x >> 5;  // 32 x 8
#pragma unroll
    for (int r = 0; r < 32; r += 8)
        tile[ty + r][tx] = W[(size_t)(by + ty + r) * NDIM + bx + tx];
    __syncthreads();
#pragma unroll
    for (int r = 0; r < 32; r += 8) {
        const float w = tile[tx][ty + r];
        const __half h = __float2half_rn(w);
        const size_t d = (size_t)(bx + ty + r) * NDIM + by + tx;
        Th[d] = h;
        Tl[d] = __float2half_rn(w - __half2float(h));
    }
}

// ---------------------------------------------------------------------------
// Kuramoto: 10 steps (rotation trick), emits fp16 phases
// ---------------------------------------------------------------------------
__global__ void __launch_bounds__(256)
kuramoto_kernel(const float* __restrict__ P, const float* __restrict__ omega,
                const float* __restrict__ Kp, __half* __restrict__ outH)
{
    const int gwarp = (blockIdx.x * blockDim.x + threadIdx.x) >> 5;
    const int lane  = threadIdx.x & 31;
    if (gwarp >= M_TOK) return;

    const float* ph = P + (size_t)gwarp * NDIM;
    const float Kv = *Kp;
    const float a_scale = DT_C * Kv * (1.0f / (float)NDIM);

    float p[16], s[16], c[16], w[16];
#pragma unroll
    for (int i = 0; i < 16; i++) {
        const int e = lane + 32 * i;
        p[i] = ph[e];
        w[i] = DT_C * omega[e];
        sincosf(p[i], &s[i], &c[i]);
    }
#pragma unroll 1
    for (int step = 0; step < NSTEPS; step++) {
        float part = 0.f;
#pragma unroll
        for (int i = 0; i < 16; i++) part += s[i];
#pragma unroll
        for (int off = 16; off > 0; off >>= 1)
            part += __shfl_xor_sync(0xFFFFFFFFu, part, off);
        const float a = a_scale * part;
#pragma unroll
        for (int i = 0; i < 16; i++) {
            const float d  = fmaf(a, c[i], w[i]);
            p[i] += d;
            const float cd = fmaf(-0.5f * d, d, 1.0f);
            const float sn = fmaf(c[i],  d, s[i] * cd);
            const float cn = fmaf(-s[i], d, c[i] * cd);
            s[i] = sn; c[i] = cn;
        }
    }
    const size_t base = (size_t)gwarp * NDIM;
#pragma unroll
    for (int i = 0; i < 16; i++)
        outH[base + lane + 32 * i] = __float2half_rn(p[i]);
}

// ---------------------------------------------------------------------------
extern "C" void kernel_launch(void* const* d_in, const int* in_sizes, int n_in,
                              void* d_out, int out_size)
{
    const float* x      = (const float*)d_in[0];
    const float* W1     = (const float*)d_in[1];
    const float* b1     = (const float*)d_in[2];
    const float* W2     = (const float*)d_in[3];
    const float* b2     = (const float*)d_in[4];
    const float* omega  = (const float*)d_in[5];
    const float* Kp     = (const float*)d_in[6];
    const float* alphap = (const float*)d_in[7];
    const float* F1     = (const float*)d_in[8];
    const float* c1     = (const float*)d_in[9];
    const float* F2     = (const float*)d_in[10];
    const float* c2     = (const float*)d_in[11];
    const float* noise  = (const float*)d_in[12];
    float* out = (float*)d_out;

    __half *actA, *actB, *wHi, *wLo;
    float* phb;
    cudaGetSymbolAddress((void**)&actA, g_act_a);
    cudaGetSymbolAddress((void**)&actB, g_act_b);
    cudaGetSymbolAddress((void**)&wHi,  g_w_hi);
    cudaGetSymbolAddress((void**)&wLo,  g_w_lo);
    cudaGetSymbolAddress((void**)&phb,  g_ph);

    cudaFuncSetAttribute(gemm_f16x2<0>, cudaFuncAttributeMaxDynamicSharedMemorySize, GEMM_SMEM);
    cudaFuncSetAttribute(gemm_f16x2<1>, cudaFuncAttributeMaxDynamicSharedMemorySize, GEMM_SMEM);
    cudaFuncSetAttribute(gemm_f16x2<2>, cudaFuncAttributeMaxDynamicSharedMemorySize, GEMM_SMEM);
    cudaFuncSetAttribute(gemm_f16x2<3>, cudaFuncAttributeMaxDynamicSharedMemorySize, GEMM_SMEM);

    const size_t WSZ = (size_t)NDIM * NDIM;
    dim3 wgrid(16, 16);
    wprep<<<wgrid, 256>>>(W1, wHi + 0*WSZ, wLo + 0*WSZ);
    wprep<<<wgrid, 256>>>(W2, wHi + 1*WSZ, wLo + 1*WSZ);
    wprep<<<wgrid, 256>>>(F1, wHi + 2*WSZ, wLo + 2*WSZ);
    wprep<<<wgrid, 256>>>(F2, wHi + 3*WSZ, wLo + 3*WSZ);
    conv_f16<<<2048, 256>>>(x, actA);

    dim3 ggrid(NDIM / BN, M_TOK / BM);   // (4, 256)

    // phases = tanh(x @ W1 + b1) -> fp16
    gemm_f16x2<1><<<ggrid, 256, GEMM_SMEM>>>(actA, wHi + 0*WSZ, wLo + 0*WSZ,
                                             b1, actB, nullptr, nullptr, nullptr);
    // phases = phases @ W2 + b2 -> fp32
    gemm_f16x2<0><<<ggrid, 256, GEMM_SMEM>>>(actB, wHi + 1*WSZ, wLo + 1*WSZ,
                                             b2, nullptr, phb, nullptr, nullptr);
    // Kuramoto -> fp16 phases
    kuramoto_kernel<<<M_TOK / 8, 256>>>(phb, omega, Kp, actA);
    // h = relu(phases @ F1 + c1) -> fp16
    gemm_f16x2<2><<<ggrid, 256, GEMM_SMEM>>>(actA, wHi + 2*WSZ, wLo + 2*WSZ,
                                             c1, actB, nullptr, nullptr, nullptr);
    // out = expand(h @ F2 + c2, noise)
    gemm_f16x2<3><<<ggrid, 256, GEMM_SMEM>>>(actB, wHi + 3*WSZ, wLo + 3*WSZ,
                                             c2, nullptr, out, noise, alphap);
}

// round 5
// speedup vs baseline: 3.2757x; 1.2846x over previous
#include <cuda_runtime.h>
#include <cuda_fp16.h>
#include <cstdint>
#include <math.h>

// ---------------------------------------------------------------------------
#define M_TOK 32768      // B*S
#define NDIM  512        // E = O
#define DT_C  0.01f
#define NSTEPS 10

#define BM 128
#define BN 128
#define BK 32
#define NCHUNK 16        // 512/32

// smem: tiles 128 rows x 80B (64B data + 16B pad -> conflict-free ldmatrix)
#define ROWB 80
#define TILE_B (128 * ROWB)          // 10240
#define OFF_A  0
#define OFF_B  (1 * TILE_B)
#define STAGE_BYTES (2 * TILE_B)     // 20480
#define NSTAGE 4
#define SM_CTRL 2048
#define GEMM_SMEM (SM_CTRL + NSTAGE * STAGE_BYTES)   // 83968

// ---------------------------------------------------------------------------
// Global scratch (allocation-free rule)
// ---------------------------------------------------------------------------
__device__ __half g_act_a[M_TOK*NDIM];   // activations ping
__device__ __half g_act_b[M_TOK*NDIM];   // activations pong
__device__ float  g_ph[M_TOK*NDIM];      // fp32 phases for Kuramoto
__device__ __half g_w[4*NDIM*NDIM];      // transposed fp16 weights

// ---------------------------------------------------------------------------
// PTX helpers (sm_80-era only)
// ---------------------------------------------------------------------------
static __device__ __forceinline__ uint32_t smem_u32(const void* p) {
    uint32_t a;
    asm("{ .reg .u64 t; cvta.to.shared.u64 t, %1; cvt.u32.u64 %0, t; }" : "=r"(a) : "l"(p));
    return a;
}
static __device__ __forceinline__ void cp16(uint32_t dst, const void* src) {
    asm volatile("cp.async.cg.shared.global [%0], [%1], 16;" :: "r"(dst), "l"(src));
}
#define CP_COMMIT() asm volatile("cp.async.commit_group;" ::: "memory")
#define CP_WAIT(n)  asm volatile("cp.async.wait_group %0;" :: "n"(n) : "memory")

#define LDSM4(r, addr) \
    asm volatile("ldmatrix.sync.aligned.m8n8.x4.shared.b16 {%0,%1,%2,%3}, [%4];" \
        : "=r"((r)[0]), "=r"((r)[1]), "=r"((r)[2]), "=r"((r)[3]) : "r"(addr))

static __device__ __forceinline__ void mma16816(float* c, const uint32_t* a,
                                                const uint32_t b0, const uint32_t b1) {
    asm volatile("mma.sync.aligned.m16n8k16.row.col.f32.f16.f16.f32 "
        "{%0,%1,%2,%3}, {%4,%5,%6,%7}, {%8,%9}, {%0,%1,%2,%3};"
        : "+f"(c[0]), "+f"(c[1]), "+f"(c[2]), "+f"(c[3])
        : "r"(a[0]), "r"(a[1]), "r"(a[2]), "r"(a[3]), "r"(b0), "r"(b1));
}

// ---------------------------------------------------------------------------
// Load one K-chunk: A (128x32 fp16) + B (128x32 fp16). 4 cp16/thread.
// ---------------------------------------------------------------------------
static __device__ __forceinline__ void load_chunk(
    uint32_t stage,
    const __half* __restrict__ A, const __half* __restrict__ B,
    int m0, int n0, int kc0, int tid)
{
#pragma unroll
    for (int i = 0; i < 2; i++) {
        const int t   = tid + i * 256;       // 0..511
        const int row = t >> 2;              // 0..127
        const int q   = t & 3;               // 16B chunk within 64B row
        const uint32_t so = (uint32_t)(row * ROWB + q * 16);
        cp16(stage + OFF_A + so, A + (size_t)(m0 + row) * NDIM + kc0 + q * 8);
        cp16(stage + OFF_B + so, B + (size_t)(n0 + row) * NDIM + kc0 + q * 8);
    }
    CP_COMMIT();
}

// ---------------------------------------------------------------------------
// fp16 GEMM: C[M,N] = act(A @ B^T + bias)
// EPI: 0 -> fp32 outF; 1 -> tanh fp16 outH; 2 -> relu fp16 outH;
//      3 -> final [m,n,4] {v, im, im, im}, im = noise*sin(alpha*n)
// ---------------------------------------------------------------------------
template<int EPI>
__global__ void __launch_bounds__(256, 1)
gemm_f16(const __half* __restrict__ A, const __half* __restrict__ B,
         const float* __restrict__ bias,
         __half* __restrict__ outH, float* __restrict__ outF,
         const float* __restrict__ noise, const float* __restrict__ alpha_p)
{
    extern __shared__ char smem[];
    const uint32_t sb = smem_u32(smem);
    const int tid  = threadIdx.x;
    const int wid  = tid >> 5;
    const int lane = tid & 31;
    const int m0 = blockIdx.y * BM;
    const int n0 = blockIdx.x * BN;

    const int wm = wid & 3;        // 4 warps along M (32 rows)
    const int wn = wid >> 2;       // 2 warps along N (64 cols)

    float* fm_s   = (float*)(smem + 64);
    float* bias_s = (float*)(smem + 1088);
    if (tid < 128) {
        bias_s[tid] = bias[n0 + tid];
        if (EPI == 3) fm_s[tid] = sinf((*alpha_p) * (float)(n0 + tid));
    }

    // prologue: 3 stages in flight
    load_chunk(sb + SM_CTRL + 0 * STAGE_BYTES, A, B, m0, n0, 0 * BK, tid);
    load_chunk(sb + SM_CTRL + 1 * STAGE_BYTES, A, B, m0, n0, 1 * BK, tid);
    load_chunk(sb + SM_CTRL + 2 * STAGE_BYTES, A, B, m0, n0, 2 * BK, tid);

    const int g  = lane >> 3;
    const int lr = lane & 7;
    const uint32_t offA = (uint32_t)((wm * 32 + (g & 1) * 8 + lr) * ROWB + (g >> 1) * 16);
    const uint32_t offB = (uint32_t)((wn * 64 + (g >> 1) * 8 + lr) * ROWB + (g & 1) * 16);

    float acc[2][8][4];
#pragma unroll
    for (int mt = 0; mt < 2; mt++)
#pragma unroll
        for (int nt = 0; nt < 8; nt++)
#pragma unroll
            for (int r = 0; r < 4; r++) acc[mt][nt][r] = 0.f;

#pragma unroll 1
    for (int c = 0; c < NCHUNK; c++) {
        CP_WAIT(2);                 // group c complete (3 groups always pending)
        __syncthreads();

        if (c + 3 < NCHUNK)
            load_chunk(sb + SM_CTRL + ((c + 3) & 3) * STAGE_BYTES,
                       A, B, m0, n0, (c + 3) * BK, tid);
        else
            CP_COMMIT();            // empty group keeps wait_group accounting exact

        const uint32_t stage = sb + SM_CTRL + (c & 3) * STAGE_BYTES;
#pragma unroll
        for (int ks = 0; ks < 2; ks++) {
            uint32_t a[2][4], b[4][4];
#pragma unroll
            for (int mt = 0; mt < 2; mt++)
                LDSM4(a[mt], stage + OFF_A + offA + mt * (16 * ROWB) + ks * 32);
#pragma unroll
            for (int bt = 0; bt < 4; bt++)
                LDSM4(b[bt], stage + OFF_B + offB + bt * (16 * ROWB) + ks * 32);
            // 16 independent MMAs (no accumulator RAW back-to-back)
#pragma unroll
            for (int mt = 0; mt < 2; mt++)
#pragma unroll
                for (int nt = 0; nt < 8; nt++) {
                    const int bt = nt >> 1, sel = (nt & 1) * 2;
                    mma16816(acc[mt][nt], a[mt], b[bt][sel], b[bt][sel + 1]);
                }
        }
    }
    __syncthreads();   // protect stage smem before reuse by epilogue staging

    // ------------------------- epilogue -------------------------
    const int rbase = wm * 32 + (lane >> 2);
    const int cbase = wn * 64 + (lane & 3) * 2;

    if (EPI == 1 || EPI == 2) {
        __half* sH = (__half*)(smem + SM_CTRL);      // stride 136 halves (272B)
#pragma unroll
        for (int mt = 0; mt < 2; mt++)
#pragma unroll
            for (int nt = 0; nt < 8; nt++) {
                const int col = cbase + nt * 8;
#pragma unroll
                for (int h = 0; h < 2; h++) {
                    const int r = rbase + mt * 16 + h * 8;
                    float v0 = acc[mt][nt][h * 2 + 0] + bias_s[col + 0];
                    float v1 = acc[mt][nt][h * 2 + 1] + bias_s[col + 1];
                    if (EPI == 1) { v0 = tanhf(v0); v1 = tanhf(v1); }
                    else          { v0 = fmaxf(v0, 0.f); v1 = fmaxf(v1, 0.f); }
                    *(__half2*)&sH[r * 136 + col] = __floats2half2_rn(v0, v1);
                }
            }
        __syncthreads();
#pragma unroll
        for (int i = 0; i < 8; i++) {
            const int t = tid + i * 256;          // 0..2047
            const int row = t >> 4, q = t & 15;
            *(uint4*)((char*)outH + ((size_t)(m0 + row) * NDIM + n0) * 2 + q * 16) =
                *(uint4*)((char*)sH + row * 272 + q * 16);
        }
    } else {
        float* sC = (float*)(smem + SM_CTRL);     // stride 132 floats
#pragma unroll
        for (int mt = 0; mt < 2; mt++)
#pragma unroll
            for (int nt = 0; nt < 8; nt++) {
                const int col = cbase + nt * 8;
#pragma unroll
                for (int h = 0; h < 2; h++) {
                    const int r = rbase + mt * 16 + h * 8;
                    sC[r * 132 + col + 0] = acc[mt][nt][h * 2 + 0] + bias_s[col + 0];
                    sC[r * 132 + col + 1] = acc[mt][nt][h * 2 + 1] + bias_s[col + 1];
                }
            }
        __syncthreads();
        if (EPI == 0) {
#pragma unroll
            for (int i = 0; i < 16; i++) {
                const int t = tid + i * 256;      // 0..4095
                const int row = t >> 5, q = t & 31;
                *(float4*)(outF + (size_t)(m0 + row) * NDIM + n0 + q * 4) =
                    *(float4*)((char*)sC + row * 528 + q * 16);
            }
        } else {   // EPI == 3
#pragma unroll 4
            for (int i = 0; i < 64; i++) {
                const int t = tid + i * 256;      // 0..16383
                const int row = t >> 7, n = t & 127;
                const float v  = sC[row * 132 + n];
                const size_t e = (size_t)(m0 + row) * NDIM + n0 + n;
                const float im = noise[e] * fm_s[n];
                *(float4*)(outF + e * 4) = make_float4(v, im, im, im);
            }
        }
    }
}

// ---------------------------------------------------------------------------
// fp32 -> fp16 (for x)
// ---------------------------------------------------------------------------
__global__ void __launch_bounds__(256)
conv_f16(const float* __restrict__ x, __half* __restrict__ o)
{
    const int n4 = M_TOK * NDIM / 4;
    for (int i = blockIdx.x * blockDim.x + threadIdx.x; i < n4; i += gridDim.x * blockDim.x) {
        const float4 v = *(const float4*)(x + i * 4);
        __half2* O = (__half2*)(o + i * 4);
        O[0] = __floats2half2_rn(v.x, v.y);
        O[1] = __floats2half2_rn(v.z, v.w);
    }
}

// ---------------------------------------------------------------------------
// Weight prep: Wt[n,k] = W[k,n] as fp16
// ---------------------------------------------------------------------------
__global__ void __launch_bounds__(256)
wprep(const float* __restrict__ W, __half* __restrict__ T)
{
    __shared__ float tile[32][33];
    const int bx = blockIdx.x * 32, by = blockIdx.y * 32;
    const int tx = threadIdx.x & 31, ty = threadIdx.x >> 5;  // 32 x 8
#pragma unroll
    for (int r = 0; r < 32; r += 8)
        tile[ty + r][tx] = W[(size_t)(by + ty + r) * NDIM + bx + tx];
    __syncthreads();
#pragma unroll
    for (int r = 0; r < 32; r += 8)
        T[(size_t)(bx + ty + r) * NDIM + by + tx] = __float2half_rn(tile[tx][ty + r]);
}

// ---------------------------------------------------------------------------
// Kuramoto: 10 steps (rotation trick), emits fp16 phases
// ---------------------------------------------------------------------------
__global__ void __launch_bounds__(256)
kuramoto_kernel(const float* __restrict__ P, const float* __restrict__ omega,
                const float* __restrict__ Kp, __half* __restrict__ outH)
{
    const int gwarp = (blockIdx.x * blockDim.x + threadIdx.x) >> 5;
    const int lane  = threadIdx.x & 31;
    if (gwarp >= M_TOK) return;

    const float* ph = P + (size_t)gwarp * NDIM;
    const float Kv = *Kp;
    const float a_scale = DT_C * Kv * (1.0f / (float)NDIM);

    float p[16], s[16], c[16], w[16];
#pragma unroll
    for (int i = 0; i < 16; i++) {
        const int e = lane + 32 * i;
        p[i] = ph[e];
        w[i] = DT_C * omega[e];
        sincosf(p[i], &s[i], &c[i]);
    }
#pragma unroll 1
    for (int step = 0; step < NSTEPS; step++) {
        float part = 0.f;
#pragma unroll
        for (int i = 0; i < 16; i++) part += s[i];
#pragma unroll
        for (int off = 16; off > 0; off >>= 1)
            part += __shfl_xor_sync(0xFFFFFFFFu, part, off);
        const float a = a_scale * part;
#pragma unroll
        for (int i = 0; i < 16; i++) {
            const float d  = fmaf(a, c[i], w[i]);
            p[i] += d;
            const float cd = fmaf(-0.5f * d, d, 1.0f);
            const float sn = fmaf(c[i],  d, s[i] * cd);
            const float cn = fmaf(-s[i], d, c[i] * cd);
            s[i] = sn; c[i] = cn;
        }
    }
    const size_t base = (size_t)gwarp * NDIM;
#pragma unroll
    for (int i = 0; i < 16; i++)
        outH[base + lane + 32 * i] = __float2half_rn(p[i]);
}

// ---------------------------------------------------------------------------
extern "C" void kernel_launch(void* const* d_in, const int* in_sizes, int n_in,
                              void* d_out, int out_size)
{
    const float* x      = (const float*)d_in[0];
    const float* W1     = (const float*)d_in[1];
    const float* b1     = (const float*)d_in[2];
    const float* W2     = (const float*)d_in[3];
    const float* b2     = (const float*)d_in[4];
    const float* omega  = (const float*)d_in[5];
    const float* Kp     = (const float*)d_in[6];
    const float* alphap = (const float*)d_in[7];
    const float* F1     = (const float*)d_in[8];
    const float* c1     = (const float*)d_in[9];
    const float* F2     = (const float*)d_in[10];
    const float* c2     = (const float*)d_in[11];
    const float* noise  = (const float*)d_in[12];
    float* out = (float*)d_out;

    __half *actA, *actB, *wT;
    float* phb;
    cudaGetSymbolAddress((void**)&actA, g_act_a);
    cudaGetSymbolAddress((void**)&actB, g_act_b);
    cudaGetSymbolAddress((void**)&wT,   g_w);
    cudaGetSymbolAddress((void**)&phb,  g_ph);

    cudaFuncSetAttribute(gemm_f16<0>, cudaFuncAttributeMaxDynamicSharedMemorySize, GEMM_SMEM);
    cudaFuncSetAttribute(gemm_f16<1>, cudaFuncAttributeMaxDynamicSharedMemorySize, GEMM_SMEM);
    cudaFuncSetAttribute(gemm_f16<2>, cudaFuncAttributeMaxDynamicSharedMemorySize, GEMM_SMEM);
    cudaFuncSetAttribute(gemm_f16<3>, cudaFuncAttributeMaxDynamicSharedMemorySize, GEMM_SMEM);

    const size_t WSZ = (size_t)NDIM * NDIM;
    dim3 wgrid(16, 16);
    wprep<<<wgrid, 256>>>(W1, wT + 0*WSZ);
    wprep<<<wgrid, 256>>>(W2, wT + 1*WSZ);
    wprep<<<wgrid, 256>>>(F1, wT + 2*WSZ);
    wprep<<<wgrid, 256>>>(F2, wT + 3*WSZ);
    conv_f16<<<2048, 256>>>(x, actA);

    dim3 ggrid(NDIM / BN, M_TOK / BM);   // (4, 256)

    // phases = tanh(x @ W1 + b1) -> fp16
    gemm_f16<1><<<ggrid, 256, GEMM_SMEM>>>(actA, wT + 0*WSZ,
                                           b1, actB, nullptr, nullptr, nullptr);
    // phases = phases @ W2 + b2 -> fp32
    gemm_f16<0><<<ggrid, 256, GEMM_SMEM>>>(actB, wT + 1*WSZ,
                                           b2, nullptr, phb, nullptr, nullptr);
    // Kuramoto -> fp16 phases
    kuramoto_kernel<<<M_TOK / 8, 256>>>(phb, omega, Kp, actA);
    // h = relu(phases @ F1 + c1) -> fp16
    gemm_f16<2><<<ggrid, 256, GEMM_SMEM>>>(actA, wT + 2*WSZ,
                                           c1, actB, nullptr, nullptr, nullptr);
    // out = expand(h @ F2 + c2, noise)
    gemm_f16<3><<<ggrid, 256, GEMM_SMEM>>>(actB, wT + 3*WSZ,
                                           c2, nullptr, out, noise, alphap);
}

// round 6
// speedup vs baseline: 3.3407x; 1.0198x over previous
#include <cuda_runtime.h>
#include <cuda_fp16.h>
#include <cstdint>
#include <math.h>

// ---------------------------------------------------------------------------
#define M_TOK 32768      // B*S
#define NDIM  512        // E = O
#define DT_C  0.01f
#define NSTEPS 10

#define BM 128
#define BN 256
#define BK 32
#define NCHUNK 16        // 512/32

// smem: rows of 80B (64B data + 16B pad -> conflict-free ldmatrix)
#define ROWB 80
#define TILE_A_B (128 * ROWB)            // 10240
#define TILE_B_B (256 * ROWB)            // 20480
#define OFF_A  0
#define OFF_B  TILE_A_B
#define STAGE_BYTES (TILE_A_B + TILE_B_B)  // 30720
#define NSTAGE 4
#define SM_CTRL 2560
// epilogue fp32 staging: 128 rows x 260 floats = 133120 B (largest user)
#define GEMM_SMEM (SM_CTRL + 133120)     // 135680; stages need 125440

// ---------------------------------------------------------------------------
// Global scratch (allocation-free rule)
// ---------------------------------------------------------------------------
__device__ __half g_act_a[M_TOK*NDIM];   // activations ping
__device__ __half g_act_b[M_TOK*NDIM];   // activations pong
__device__ float  g_ph[M_TOK*NDIM];      // fp32 phases for Kuramoto
__device__ __half g_w[4*NDIM*NDIM];      // transposed fp16 weights

// ---------------------------------------------------------------------------
// PTX helpers (sm_80-era only)
// ---------------------------------------------------------------------------
static __device__ __forceinline__ uint32_t smem_u32(const void* p) {
    uint32_t a;
    asm("{ .reg .u64 t; cvta.to.shared.u64 t, %1; cvt.u32.u64 %0, t; }" : "=r"(a) : "l"(p));
    return a;
}
static __device__ __forceinline__ void cp16(uint32_t dst, const void* src) {
    asm volatile("cp.async.cg.shared.global [%0], [%1], 16;" :: "r"(dst), "l"(src));
}
#define CP_COMMIT() asm volatile("cp.async.commit_group;" ::: "memory")
#define CP_WAIT(n)  asm volatile("cp.async.wait_group %0;" :: "n"(n) : "memory")

#define LDSM4(r, addr) \
    asm volatile("ldmatrix.sync.aligned.m8n8.x4.shared.b16 {%0,%1,%2,%3}, [%4];" \
        : "=r"((r)[0]), "=r"((r)[1]), "=r"((r)[2]), "=r"((r)[3]) : "r"(addr))

static __device__ __forceinline__ void mma16816(float* c, const uint32_t* a,
                                                const uint32_t b0, const uint32_t b1) {
    asm volatile("mma.sync.aligned.m16n8k16.row.col.f32.f16.f16.f32 "
        "{%0,%1,%2,%3}, {%4,%5,%6,%7}, {%8,%9}, {%0,%1,%2,%3};"
        : "+f"(c[0]), "+f"(c[1]), "+f"(c[2]), "+f"(c[3])
        : "r"(a[0]), "r"(a[1]), "r"(a[2]), "r"(a[3]), "r"(b0), "r"(b1));
}

// ---------------------------------------------------------------------------
// Load one K-chunk: A 128x32 fp16 + B 256x32 fp16. 6 cp16/thread.
// ---------------------------------------------------------------------------
static __device__ __forceinline__ void load_chunk(
    uint32_t stage,
    const __half* __restrict__ A, const __half* __restrict__ B,
    int m0, int n0, int kc0, int tid)
{
#pragma unroll
    for (int i = 0; i < 2; i++) {
        const int t   = tid + i * 256;       // 0..511
        const int row = t >> 2;              // 0..127
        const int q   = t & 3;
        cp16(stage + OFF_A + (uint32_t)(row * ROWB + q * 16),
             A + (size_t)(m0 + row) * NDIM + kc0 + q * 8);
    }
#pragma unroll
    for (int i = 0; i < 4; i++) {
        const int t   = tid + i * 256;       // 0..1023
        const int row = t >> 2;              // 0..255
        const int q   = t & 3;
        cp16(stage + OFF_B + (uint32_t)(row * ROWB + q * 16),
             B + (size_t)(n0 + row) * NDIM + kc0 + q * 8);
    }
    CP_COMMIT();
}

// ---------------------------------------------------------------------------
// fp16 GEMM: C[M,N] = act(A @ B^T + bias); CTA tile 128x256, warp tile 64x64
// EPI: 0 -> fp32 outF; 1 -> tanh fp16 outH; 2 -> relu fp16 outH;
//      3 -> final [m,n,4] {v, im, im, im}, im = noise*sin(alpha*n)
// ---------------------------------------------------------------------------
template<int EPI>
__global__ void __launch_bounds__(256, 1)
gemm_f16(const __half* __restrict__ A, const __half* __restrict__ B,
         const float* __restrict__ bias,
         __half* __restrict__ outH, float* __restrict__ outF,
         const float* __restrict__ noise, const float* __restrict__ alpha_p)
{
    extern __shared__ char smem[];
    const uint32_t sb = smem_u32(smem);
    const int tid  = threadIdx.x;
    const int wid  = tid >> 5;
    const int lane = tid & 31;
    const int m0 = blockIdx.y * BM;
    const int n0 = blockIdx.x * BN;

    const int wm = wid & 1;        // 2 warps along M (64 rows each)
    const int wn = wid >> 1;       // 4 warps along N (64 cols each)

    float* bias_s = (float*)(smem + 64);     // 256 floats: 64..1088
    float* fm_s   = (float*)(smem + 1088);   // 256 floats: 1088..2112
    bias_s[tid] = bias[n0 + tid];
    if (EPI == 3) fm_s[tid] = sinf((*alpha_p) * (float)(n0 + tid));

    // prologue: 3 stages in flight
    load_chunk(sb + SM_CTRL + 0 * STAGE_BYTES, A, B, m0, n0, 0 * BK, tid);
    load_chunk(sb + SM_CTRL + 1 * STAGE_BYTES, A, B, m0, n0, 1 * BK, tid);
    load_chunk(sb + SM_CTRL + 2 * STAGE_BYTES, A, B, m0, n0, 2 * BK, tid);

    const int g  = lane >> 3;
    const int lr = lane & 7;
    const uint32_t offA = (uint32_t)((wm * 64 + (g & 1) * 8 + lr) * ROWB + (g >> 1) * 16);
    const uint32_t offB = (uint32_t)((wn * 64 + (g >> 1) * 8 + lr) * ROWB + (g & 1) * 16);

    float acc[4][8][4];
#pragma unroll
    for (int mt = 0; mt < 4; mt++)
#pragma unroll
        for (int nt = 0; nt < 8; nt++)
#pragma unroll
            for (int r = 0; r < 4; r++) acc[mt][nt][r] = 0.f;

#pragma unroll 1
    for (int c = 0; c < NCHUNK; c++) {
        CP_WAIT(2);                 // group c complete (3 groups pending)
        __syncthreads();

        if (c + 3 < NCHUNK)
            load_chunk(sb + SM_CTRL + ((c + 3) & 3) * STAGE_BYTES,
                       A, B, m0, n0, (c + 3) * BK, tid);
        else
            CP_COMMIT();            // empty group keeps accounting exact

        const uint32_t stage = sb + SM_CTRL + (c & 3) * STAGE_BYTES;
#pragma unroll
        for (int ks = 0; ks < 2; ks++) {
            uint32_t a[4][4], b[4][4];
#pragma unroll
            for (int mt = 0; mt < 4; mt++)
                LDSM4(a[mt], stage + OFF_A + offA + mt * (16 * ROWB) + ks * 32);
#pragma unroll
            for (int bt = 0; bt < 4; bt++)
                LDSM4(b[bt], stage + OFF_B + offB + bt * (16 * ROWB) + ks * 32);
#pragma unroll
            for (int mt = 0; mt < 4; mt++)
#pragma unroll
                for (int nt = 0; nt < 8; nt++) {
                    const int bt = nt >> 1, sel = (nt & 1) * 2;
                    mma16816(acc[mt][nt], a[mt], b[bt][sel], b[bt][sel + 1]);
                }
        }
    }
    __syncthreads();   // stages dead; reuse smem for epilogue staging

    // ------------------------- epilogue -------------------------
    const int rbase = wm * 64 + (lane >> 2);
    const int cbase = wn * 64 + (lane & 3) * 2;

    if (EPI == 1 || EPI == 2) {
        __half* sH = (__half*)(smem + SM_CTRL);      // stride 264 halves (528B)
#pragma unroll
        for (int mt = 0; mt < 4; mt++)
#pragma unroll
            for (int nt = 0; nt < 8; nt++) {
                const int col = cbase + nt * 8;
#pragma unroll
                for (int h = 0; h < 2; h++) {
                    const int r = rbase + mt * 16 + h * 8;
                    float v0 = acc[mt][nt][h * 2 + 0] + bias_s[col + 0];
                    float v1 = acc[mt][nt][h * 2 + 1] + bias_s[col + 1];
                    if (EPI == 1) { v0 = tanhf(v0); v1 = tanhf(v1); }
                    else          { v0 = fmaxf(v0, 0.f); v1 = fmaxf(v1, 0.f); }
                    *(__half2*)&sH[r * 264 + col] = __floats2half2_rn(v0, v1);
                }
            }
        __syncthreads();
#pragma unroll
        for (int i = 0; i < 16; i++) {
            const int t = tid + i * 256;          // 0..4095
            const int row = t >> 5, q = t & 31;   // 32 uint4 per 512B row
            *(uint4*)((char*)outH + ((size_t)(m0 + row) * NDIM + n0) * 2 + q * 16) =
                *(uint4*)((char*)sH + row * 528 + q * 16);
        }
    } else {
        float* sC = (float*)(smem + SM_CTRL);     // stride 260 floats (1040B)
#pragma unroll
        for (int mt = 0; mt < 4; mt++)
#pragma unroll
            for (int nt = 0; nt < 8; nt++) {
                const int col = cbase + nt * 8;
#pragma unroll
                for (int h = 0; h < 2; h++) {
                    const int r = rbase + mt * 16 + h * 8;
                    sC[r * 260 + col + 0] = acc[mt][nt][h * 2 + 0] + bias_s[col + 0];
                    sC[r * 260 + col + 1] = acc[mt][nt][h * 2 + 1] + bias_s[col + 1];
                }
            }
        __syncthreads();
        if (EPI == 0) {
#pragma unroll
            for (int i = 0; i < 32; i++) {
                const int t = tid + i * 256;      // 0..8191
                const int row = t >> 6, q = t & 63;
                *(float4*)(outF + (size_t)(m0 + row) * NDIM + n0 + q * 4) =
                    *(float4*)((char*)sC + row * 1040 + q * 16);
            }
        } else {   // EPI == 3
#pragma unroll 4
            for (int i = 0; i < 128; i++) {
                const int t = tid + i * 256;      // 0..32767
                const int row = t >> 8, n = t & 255;
                const float v  = sC[row * 260 + n];
                const size_t e = (size_t)(m0 + row) * NDIM + n0 + n;
                const float im = noise[e] * fm_s[n];
                *(float4*)(outF + e * 4) = make_float4(v, im, im, im);
            }
        }
    }
}

// ---------------------------------------------------------------------------
// fp32 -> fp16 (for x)
// ---------------------------------------------------------------------------
__global__ void __launch_bounds__(256)
conv_f16(const float* __restrict__ x, __half* __restrict__ o)
{
    const int n4 = M_TOK * NDIM / 4;
    for (int i = blockIdx.x * blockDim.x + threadIdx.x; i < n4; i += gridDim.x * blockDim.x) {
        const float4 v = *(const float4*)(x + i * 4);
        __half2* O = (__half2*)(o + i * 4);
        O[0] = __floats2half2_rn(v.x, v.y);
        O[1] = __floats2half2_rn(v.z, v.w);
    }
}

// ---------------------------------------------------------------------------
// Weight prep (all 4 weights in one launch): Wt[n,k] = W[k,n] as fp16
// ---------------------------------------------------------------------------
__global__ void __launch_bounds__(256)
wprep4(const float* __restrict__ W1, const float* __restrict__ W2,
       const float* __restrict__ F1, const float* __restrict__ F2,
       __half* __restrict__ T)
{
    const float* W = (blockIdx.z == 0) ? W1 : (blockIdx.z == 1) ? W2
                   : (blockIdx.z == 2) ? F1 : F2;
    __half* Tz = T + (size_t)blockIdx.z * NDIM * NDIM;

    __shared__ float tile[32][33];
    const int bx = blockIdx.x * 32, by = blockIdx.y * 32;
    const int tx = threadIdx.x & 31, ty = threadIdx.x >> 5;  // 32 x 8
#pragma unroll
    for (int r = 0; r < 32; r += 8)
        tile[ty + r][tx] = W[(size_t)(by + ty + r) * NDIM + bx + tx];
    __syncthreads();
#pragma unroll
    for (int r = 0; r < 32; r += 8)
        Tz[(size_t)(bx + ty + r) * NDIM + by + tx] = __float2half_rn(tile[tx][ty + r]);
}

// ---------------------------------------------------------------------------
// Kuramoto: 10 steps (rotation trick), emits fp16 phases
// ---------------------------------------------------------------------------
__global__ void __launch_bounds__(256)
kuramoto_kernel(const float* __restrict__ P, const float* __restrict__ omega,
                const float* __restrict__ Kp, __half* __restrict__ outH)
{
    const int gwarp = (blockIdx.x * blockDim.x + threadIdx.x) >> 5;
    const int lane  = threadIdx.x & 31;
    if (gwarp >= M_TOK) return;

    const float* ph = P + (size_t)gwarp * NDIM;
    const float Kv = *Kp;
    const float a_scale = DT_C * Kv * (1.0f / (float)NDIM);

    float p[16], s[16], c[16], w[16];
#pragma unroll
    for (int i = 0; i < 16; i++) {
        const int e = lane + 32 * i;
        p[i] = ph[e];
        w[i] = DT_C * omega[e];
        sincosf(p[i], &s[i], &c[i]);
    }
#pragma unroll 1
    for (int step = 0; step < NSTEPS; step++) {
        float part = 0.f;
#pragma unroll
        for (int i = 0; i < 16; i++) part += s[i];
#pragma unroll
        for (int off = 16; off > 0; off >>= 1)
            part += __shfl_xor_sync(0xFFFFFFFFu, part, off);
        const float a = a_scale * part;
#pragma unroll
        for (int i = 0; i < 16; i++) {
            const float d  = fmaf(a, c[i], w[i]);
            p[i] += d;
            const float cd = fmaf(-0.5f * d, d, 1.0f);
            const float sn = fmaf(c[i],  d, s[i] * cd);
            const float cn = fmaf(-s[i], d, c[i] * cd);
            s[i] = sn; c[i] = cn;
        }
    }
    const size_t base = (size_t)gwarp * NDIM;
#pragma unroll
    for (int i = 0; i < 16; i++)
        outH[base + lane + 32 * i] = __float2half_rn(p[i]);
}

// ---------------------------------------------------------------------------
extern "C" void kernel_launch(void* const* d_in, const int* in_sizes, int n_in,
                              void* d_out, int out_size)
{
    const float* x      = (const float*)d_in[0];
    const float* W1     = (const float*)d_in[1];
    const float* b1     = (const float*)d_in[2];
    const float* W2     = (const float*)d_in[3];
    const float* b2     = (const float*)d_in[4];
    const float* omega  = (const float*)d_in[5];
    const float* Kp     = (const float*)d_in[6];
    const float* alphap = (const float*)d_in[7];
    const float* F1     = (const float*)d_in[8];
    const float* c1     = (const float*)d_in[9];
    const float* F2     = (const float*)d_in[10];
    const float* c2     = (const float*)d_in[11];
    const float* noise  = (const float*)d_in[12];
    float* out = (float*)d_out;

    __half *actA, *actB, *wT;
    float* phb;
    cudaGetSymbolAddress((void**)&actA, g_act_a);
    cudaGetSymbolAddress((void**)&actB, g_act_b);
    cudaGetSymbolAddress((void**)&wT,   g_w);
    cudaGetSymbolAddress((void**)&phb,  g_ph);

    cudaFuncSetAttribute(gemm_f16<0>, cudaFuncAttributeMaxDynamicSharedMemorySize, GEMM_SMEM);
    cudaFuncSetAttribute(gemm_f16<1>, cudaFuncAttributeMaxDynamicSharedMemorySize, GEMM_SMEM);
    cudaFuncSetAttribute(gemm_f16<2>, cudaFuncAttributeMaxDynamicSharedMemorySize, GEMM_SMEM);
    cudaFuncSetAttribute(gemm_f16<3>, cudaFuncAttributeMaxDynamicSharedMemorySize, GEMM_SMEM);

    const size_t WSZ = (size_t)NDIM * NDIM;
    wprep4<<<dim3(16, 16, 4), 256>>>(W1, W2, F1, F2, wT);
    conv_f16<<<2048, 256>>>(x, actA);

    dim3 ggrid(NDIM / BN, M_TOK / BM);   // (2, 256)

    // phases = tanh(x @ W1 + b1) -> fp16
    gemm_f16<1><<<ggrid, 256, GEMM_SMEM>>>(actA, wT + 0*WSZ,
                                           b1, actB, nullptr, nullptr, nullptr);
    // phases = phases @ W2 + b2 -> fp32
    gemm_f16<0><<<ggrid, 256, GEMM_SMEM>>>(actB, wT + 1*WSZ,
                                           b2, nullptr, phb, nullptr, nullptr);
    // Kuramoto -> fp16 phases
    kuramoto_kernel<<<M_TOK / 8, 256>>>(phb, omega, Kp, actA);
    // h = relu(phases @ F1 + c1) -> fp16
    gemm_f16<2><<<ggrid, 256, GEMM_SMEM>>>(actA, wT + 2*WSZ,
                                           c1, actB, nullptr, nullptr, nullptr);
    // out = expand(h @ F2 + c2, noise)
    gemm_f16<3><<<ggrid, 256, GEMM_SMEM>>>(actB, wT + 3*WSZ,
                                           c2, nullptr, out, noise, alphap);
}

// round 7
// speedup vs baseline: 3.6721x; 1.0992x over previous
#include <cuda_runtime.h>
#include <cuda_fp16.h>
#include <cstdint>
#include <math.h>

// ---------------------------------------------------------------------------
#define M_TOK 32768      // B*S
#define NDIM  512        // E = O
#define DT_C  0.01f
#define NSTEPS 10

#define BM 128
#define BN 128
#define BK 32
#define NCHUNK 16        // 512/32
#define NTHR 128         // 4 warps

// smem: rows of 80B (64B data + 16B pad -> conflict-free ldmatrix)
#define ROWB 80
#define TILE_BYTES (128 * ROWB)            // 10240
#define OFF_A  0
#define OFF_B  TILE_BYTES
#define STAGE_BYTES (2 * TILE_BYTES)       // 20480 (A+B)
#define SM_CTRL 2560
// epilogue fp32 staging (EPI0/3): 128 rows x 132 floats = 67584 B (largest)
#define GEMM_SMEM (SM_CTRL + 67584)        // 70144; stages need 2*20480=40960

// ---------------------------------------------------------------------------
// Global scratch (allocation-free rule)
// ---------------------------------------------------------------------------
__device__ __half g_act_a[M_TOK*NDIM];   // activations ping
__device__ __half g_act_b[M_TOK*NDIM];   // activations pong
__device__ float  g_ph[M_TOK*NDIM];      // fp32 phases for Kuramoto
__device__ __half g_w[4*NDIM*NDIM];      // transposed fp16 weights

// ---------------------------------------------------------------------------
// PTX helpers (sm_80-era only)
// ---------------------------------------------------------------------------
static __device__ __forceinline__ uint32_t smem_u32(const void* p) {
    uint32_t a;
    asm("{ .reg .u64 t; cvta.to.shared.u64 t, %1; cvt.u32.u64 %0, t; }" : "=r"(a) : "l"(p));
    return a;
}
static __device__ __forceinline__ void cp16(uint32_t dst, const void* src) {
    asm volatile("cp.async.cg.shared.global [%0], [%1], 16;" :: "r"(dst), "l"(src));
}
#define CP_COMMIT() asm volatile("cp.async.commit_group;" ::: "memory")
#define CP_WAIT(n)  asm volatile("cp.async.wait_group %0;" :: "n"(n) : "memory")

#define LDSM4(r, addr) \
    asm volatile("ldmatrix.sync.aligned.m8n8.x4.shared.b16 {%0,%1,%2,%3}, [%4];" \
        : "=r"((r)[0]), "=r"((r)[1]), "=r"((r)[2]), "=r"((r)[3]) : "r"(addr))

static __device__ __forceinline__ void mma16816(float* c, const uint32_t* a,
                                                const uint32_t b0, const uint32_t b1) {
    asm volatile("mma.sync.aligned.m16n8k16.row.col.f32.f16.f16.f32 "
        "{%0,%1,%2,%3}, {%4,%5,%6,%7}, {%8,%9}, {%0,%1,%2,%3};"
        : "+f"(c[0]), "+f"(c[1]), "+f"(c[2]), "+f"(c[3])
        : "r"(a[0]), "r"(a[1]), "r"(a[2]), "r"(a[3]), "r"(b0), "r"(b1));
}

// fast tanh via MUFU: 1 - 2/(exp(2x)+1); saturates correctly at +-inf
static __device__ __forceinline__ float ftanh(float x) {
    float e, r;
    const float u = x * 2.8853900817779268f;   // 2*log2(e)
    asm("ex2.approx.f32 %0, %1;" : "=f"(e) : "f"(u));
    asm("rcp.approx.f32 %0, %1;" : "=f"(r) : "f"(e + 1.0f));
    return fmaf(-2.0f, r, 1.0f);
}

// ---------------------------------------------------------------------------
// Load one K-chunk: A 128x32 fp16 + B 128x32 fp16. 8 cp16/thread (128 thr).
// ---------------------------------------------------------------------------
static __device__ __forceinline__ void load_chunk(
    uint32_t stage,
    const __half* __restrict__ A, const __half* __restrict__ B,
    int m0, int n0, int kc0, int tid)
{
#pragma unroll
    for (int i = 0; i < 4; i++) {
        const int t   = tid + i * NTHR;      // 0..511
        const int row = t >> 2;              // 0..127
        const int q   = t & 3;
        const uint32_t so = (uint32_t)(row * ROWB + q * 16);
        cp16(stage + OFF_A + so, A + (size_t)(m0 + row) * NDIM + kc0 + q * 8);
        cp16(stage + OFF_B + so, B + (size_t)(n0 + row) * NDIM + kc0 + q * 8);
    }
    CP_COMMIT();
}

// ---------------------------------------------------------------------------
// fp16 GEMM: C[M,N] = act(A @ B^T + bias); CTA 128x128, 4 warps of 64x64
// EPI: 0 -> fp32 outF; 1 -> tanh fp16 outH; 2 -> relu fp16 outH;
//      3 -> final [m,n,4] {v, im, im, im}, im = noise*sin(alpha*n)
// ---------------------------------------------------------------------------
template<int EPI>
__global__ void __launch_bounds__(NTHR, 2)
gemm_f16(const __half* __restrict__ A, const __half* __restrict__ B,
         const float* __restrict__ bias,
         __half* __restrict__ outH, float* __restrict__ outF,
         const float* __restrict__ noise, const float* __restrict__ alpha_p)
{
    extern __shared__ char smem[];
    const uint32_t sb = smem_u32(smem);
    const int tid  = threadIdx.x;
    const int wid  = tid >> 5;
    const int lane = tid & 31;
    const int m0 = blockIdx.y * BM;
    const int n0 = blockIdx.x * BN;

    const int wm = wid & 1;        // 2 warps along M (64 rows each)
    const int wn = wid >> 1;       // 2 warps along N (64 cols each)

    float* bias_s = (float*)(smem + 64);     // 128 floats
    float* fm_s   = (float*)(smem + 576);    // 128 floats
    bias_s[tid] = bias[n0 + tid];
    if (EPI == 3) fm_s[tid] = sinf((*alpha_p) * (float)(n0 + tid));

    // prologue: both buffers in flight
    load_chunk(sb + SM_CTRL + 0 * STAGE_BYTES, A, B, m0, n0, 0 * BK, tid);
    load_chunk(sb + SM_CTRL + 1 * STAGE_BYTES, A, B, m0, n0, 1 * BK, tid);

    const int g  = lane >> 3;
    const int lr = lane & 7;
    const uint32_t offA = (uint32_t)((wm * 64 + (g & 1) * 8 + lr) * ROWB + (g >> 1) * 16);
    const uint32_t offB = (uint32_t)((wn * 64 + (g >> 1) * 8 + lr) * ROWB + (g & 1) * 16);

    float acc[4][8][4];
#pragma unroll
    for (int mt = 0; mt < 4; mt++)
#pragma unroll
        for (int nt = 0; nt < 8; nt++)
#pragma unroll
            for (int r = 0; r < 4; r++) acc[mt][nt][r] = 0.f;

#pragma unroll 1
    for (int c = 0; c < NCHUNK; c++) {
        CP_WAIT(1);                 // chunk c landed (chunk c+1 may be pending)
        __syncthreads();

        const uint32_t stage = sb + SM_CTRL + (c & 1) * STAGE_BYTES;
#pragma unroll
        for (int ks = 0; ks < 2; ks++) {
            uint32_t a[4][4], b[4][4];
#pragma unroll
            for (int mt = 0; mt < 4; mt++)
                LDSM4(a[mt], stage + OFF_A + offA + mt * (16 * ROWB) + ks * 32);
#pragma unroll
            for (int bt = 0; bt < 4; bt++)
                LDSM4(b[bt], stage + OFF_B + offB + bt * (16 * ROWB) + ks * 32);
#pragma unroll
            for (int mt = 0; mt < 4; mt++)
#pragma unroll
                for (int nt = 0; nt < 8; nt++) {
                    const int bt = nt >> 1, sel = (nt & 1) * 2;
                    mma16816(acc[mt][nt], a[mt], b[bt][sel], b[bt][sel + 1]);
                }
        }
        __syncthreads();            // all warps done reading buffer (c&1)

        if (c + 2 < NCHUNK)
            load_chunk(sb + SM_CTRL + (c & 1) * STAGE_BYTES,
                       A, B, m0, n0, (c + 2) * BK, tid);
        else
            CP_COMMIT();            // empty group keeps accounting exact
    }

    // ------------------------- epilogue -------------------------
    const int rbase = wm * 64 + (lane >> 2);
    const int cbase = wn * 64 + (lane & 3) * 2;

    if (EPI == 1 || EPI == 2) {
        __half* sH = (__half*)(smem + SM_CTRL);      // stride 136 halves (272B)
#pragma unroll
        for (int mt = 0; mt < 4; mt++)
#pragma unroll
            for (int nt = 0; nt < 8; nt++) {
                const int col = cbase + nt * 8;
#pragma unroll
                for (int h = 0; h < 2; h++) {
                    const int r = rbase + mt * 16 + h * 8;
                    float v0 = acc[mt][nt][h * 2 + 0] + bias_s[col + 0];
                    float v1 = acc[mt][nt][h * 2 + 1] + bias_s[col + 1];
                    if (EPI == 1) { v0 = ftanh(v0); v1 = ftanh(v1); }
                    else          { v0 = fmaxf(v0, 0.f); v1 = fmaxf(v1, 0.f); }
                    *(__half2*)&sH[r * 136 + col] = __floats2half2_rn(v0, v1);
                }
            }
        __syncthreads();
#pragma unroll
        for (int i = 0; i < 16; i++) {
            const int t = tid + i * NTHR;         // 0..2047
            const int row = t >> 4, q = t & 15;   // 16 uint4 per 256B row
            *(uint4*)((char*)outH + ((size_t)(m0 + row) * NDIM + n0) * 2 + q * 16) =
                *(uint4*)((char*)sH + row * 272 + q * 16);
        }
    } else {
        float* sC = (float*)(smem + SM_CTRL);     // stride 132 floats (528B)
#pragma unroll
        for (int mt = 0; mt < 4; mt++)
#pragma unroll
            for (int nt = 0; nt < 8; nt++) {
                const int col = cbase + nt * 8;
#pragma unroll
                for (int h = 0; h < 2; h++) {
                    const int r = rbase + mt * 16 + h * 8;
                    sC[r * 132 + col + 0] = acc[mt][nt][h * 2 + 0] + bias_s[col + 0];
                    sC[r * 132 + col + 1] = acc[mt][nt][h * 2 + 1] + bias_s[col + 1];
                }
            }
        __syncthreads();
        if (EPI == 0) {
#pragma unroll
            for (int i = 0; i < 32; i++) {
                const int t = tid + i * NTHR;     // 0..4095
                const int row = t >> 5, q = t & 31;
                *(float4*)(outF + (size_t)(m0 + row) * NDIM + n0 + q * 4) =
                    *(float4*)((char*)sC + row * 528 + q * 16);
            }
        } else {   // EPI == 3
#pragma unroll 4
            for (int i = 0; i < 128; i++) {
                const int t = tid + i * NTHR;     // 0..16383
                const int row = t >> 7, n = t & 127;
                const float v  = sC[row * 132 + n];
                const size_t e = (size_t)(m0 + row) * NDIM + n0 + n;
                const float im = noise[e] * fm_s[n];
                *(float4*)(outF + e * 4) = make_float4(v, im, im, im);
            }
        }
    }
}

// ---------------------------------------------------------------------------
// fp32 -> fp16 (for x)
// ---------------------------------------------------------------------------
__global__ void __launch_bounds__(256)
conv_f16(const float* __restrict__ x, __half* __restrict__ o)
{
    const int n4 = M_TOK * NDIM / 4;
    for (int i = blockIdx.x * blockDim.x + threadIdx.x; i < n4; i += gridDim.x * blockDim.x) {
        const float4 v = *(const float4*)(x + i * 4);
        __half2* O = (__half2*)(o + i * 4);
        O[0] = __floats2half2_rn(v.x, v.y);
        O[1] = __floats2half2_rn(v.z, v.w);
    }
}

// ---------------------------------------------------------------------------
// Weight prep (all 4 weights in one launch): Wt[n,k] = W[k,n] as fp16
// ---------------------------------------------------------------------------
__global__ void __launch_bounds__(256)
wprep4(const float* __restrict__ W1, const float* __restrict__ W2,
       const float* __restrict__ F1, const float* __restrict__ F2,
       __half* __restrict__ T)
{
    const float* W = (blockIdx.z == 0) ? W1 : (blockIdx.z == 1) ? W2
                   : (blockIdx.z == 2) ? F1 : F2;
    __half* Tz = T + (size_t)blockIdx.z * NDIM * NDIM;

    __shared__ float tile[32][33];
    const int bx = blockIdx.x * 32, by = blockIdx.y * 32;
    const int tx = threadIdx.x & 31, ty = threadIdx.x >> 5;  // 32 x 8
#pragma unroll
    for (int r = 0; r < 32; r += 8)
        tile[ty + r][tx] = W[(size_t)(by + ty + r) * NDIM + bx + tx];
    __syncthreads();
#pragma unroll
    for (int r = 0; r < 32; r += 8)
        Tz[(size_t)(bx + ty + r) * NDIM + by + tx] = __float2half_rn(tile[tx][ty + r]);
}

// ---------------------------------------------------------------------------
// Kuramoto: 10 steps (rotation trick), emits fp16 phases
// ---------------------------------------------------------------------------
__global__ void __launch_bounds__(256)
kuramoto_kernel(const float* __restrict__ P, const float* __restrict__ omega,
                const float* __restrict__ Kp, __half* __restrict__ outH)
{
    const int gwarp = (blockIdx.x * blockDim.x + threadIdx.x) >> 5;
    const int lane  = threadIdx.x & 31;
    if (gwarp >= M_TOK) return;

    const float* ph = P + (size_t)gwarp * NDIM;
    const float Kv = *Kp;
    const float a_scale = DT_C * Kv * (1.0f / (float)NDIM);

    float p[16], s[16], c[16], w[16];
#pragma unroll
    for (int i = 0; i < 16; i++) {
        const int e = lane + 32 * i;
        p[i] = ph[e];
        w[i] = DT_C * omega[e];
        sincosf(p[i], &s[i], &c[i]);
    }
#pragma unroll 1
    for (int step = 0; step < NSTEPS; step++) {
        float part = 0.f;
#pragma unroll
        for (int i = 0; i < 16; i++) part += s[i];
#pragma unroll
        for (int off = 16; off > 0; off >>= 1)
            part += __shfl_xor_sync(0xFFFFFFFFu, part, off);
        const float a = a_scale * part;
#pragma unroll
        for (int i = 0; i < 16; i++) {
            const float d  = fmaf(a, c[i], w[i]);
            p[i] += d;
            const float cd = fmaf(-0.5f * d, d, 1.0f);
            const float sn = fmaf(c[i],  d, s[i] * cd);
            const float cn = fmaf(-s[i], d, c[i] * cd);
            s[i] = sn; c[i] = cn;
        }
    }
    const size_t base = (size_t)gwarp * NDIM;
#pragma unroll
    for (int i = 0; i < 16; i++)
        outH[base + lane + 32 * i] = __float2half_rn(p[i]);
}

// ---------------------------------------------------------------------------
extern "C" void kernel_launch(void* const* d_in, const int* in_sizes, int n_in,
                              void* d_out, int out_size)
{
    const float* x      = (const float*)d_in[0];
    const float* W1     = (const float*)d_in[1];
    const float* b1     = (const float*)d_in[2];
    const float* W2     = (const float*)d_in[3];
    const float* b2     = (const float*)d_in[4];
    const float* omega  = (const float*)d_in[5];
    const float* Kp     = (const float*)d_in[6];
    const float* alphap = (const float*)d_in[7];
    const float* F1     = (const float*)d_in[8];
    const float* c1     = (const float*)d_in[9];
    const float* F2     = (const float*)d_in[10];
    const float* c2     = (const float*)d_in[11];
    const float* noise  = (const float*)d_in[12];
    float* out = (float*)d_out;

    __half *actA, *actB, *wT;
    float* phb;
    cudaGetSymbolAddress((void**)&actA, g_act_a);
    cudaGetSymbolAddress((void**)&actB, g_act_b);
    cudaGetSymbolAddress((void**)&wT,   g_w);
    cudaGetSymbolAddress((void**)&phb,  g_ph);

    cudaFuncSetAttribute(gemm_f16<0>, cudaFuncAttributeMaxDynamicSharedMemorySize, GEMM_SMEM);
    cudaFuncSetAttribute(gemm_f16<1>, cudaFuncAttributeMaxDynamicSharedMemorySize, GEMM_SMEM);
    cudaFuncSetAttribute(gemm_f16<2>, cudaFuncAttributeMaxDynamicSharedMemorySize, GEMM_SMEM);
    cudaFuncSetAttribute(gemm_f16<3>, cudaFuncAttributeMaxDynamicSharedMemorySize, GEMM_SMEM);

    const size_t WSZ = (size_t)NDIM * NDIM;
    wprep4<<<dim3(16, 16, 4), 256>>>(W1, W2, F1, F2, wT);
    conv_f16<<<2048, 256>>>(x, actA);

    dim3 ggrid(NDIM / BN, M_TOK / BM);   // (4, 256) = 1024 CTAs

    // phases = tanh(x @ W1 + b1) -> fp16
    gemm_f16<1><<<ggrid, NTHR, GEMM_SMEM>>>(actA, wT + 0*WSZ,
                                            b1, actB, nullptr, nullptr, nullptr);
    // phases = phases @ W2 + b2 -> fp32
    gemm_f16<0><<<ggrid, NTHR, GEMM_SMEM>>>(actB, wT + 1*WSZ,
                                            b2, nullptr, phb, nullptr, nullptr);
    // Kuramoto -> fp16 phases
    kuramoto_kernel<<<M_TOK / 8, 256>>>(phb, omega, Kp, actA);
    // h = relu(phases @ F1 + c1) -> fp16
    gemm_f16<2><<<ggrid, NTHR, GEMM_SMEM>>>(actA, wT + 2*WSZ,
                                            c1, actB, nullptr, nullptr, nullptr);
    // out = expand(h @ F2 + c2, noise)
    gemm_f16<3><<<ggrid, NTHR, GEMM_SMEM>>>(actB, wT + 3*WSZ,
                                            c2, nullptr, out, noise, alphap);
}

// round 8
// speedup vs baseline: 4.6201x; 1.2582x over previous
#include <cuda_runtime.h>
#include <cuda_fp16.h>
#include <cstdint>
#include <math.h>

// ---------------------------------------------------------------------------
#define M_TOK 32768      // B*S
#define NDIM  512        // E = O
#define DT_C  0.01f
#define NSTEPS 10

#define BM 128
#define BN 128
#define BK 32
#define NCHUNK 16        // 512/32
#define NTHR 128         // 4 warps
#define NSTAGE 4

// smem: rows of 80B (64B data + 16B pad -> conflict-free ldmatrix)
#define ROWB 80
#define TILE_BYTES (128 * ROWB)            // 10240
#define OFF_A  0
#define OFF_B  TILE_BYTES
#define STAGE_BYTES (2 * TILE_BYTES)       // 20480 (A+B)
#define SM_CTRL 2560
// stage area 4*20480 = 81920; epilogue staging (128 x 132 fl = 67584) reuses it
#define GEMM_SMEM (SM_CTRL + NSTAGE * STAGE_BYTES)   // 84480

// ---------------------------------------------------------------------------
// Global scratch (allocation-free rule)
// ---------------------------------------------------------------------------
__device__ __half g_act_a[M_TOK*NDIM];   // activations ping
__device__ __half g_act_b[M_TOK*NDIM];   // activations pong
__device__ float  g_ph[M_TOK*NDIM];      // fp32 phases for Kuramoto
__device__ __half g_w[4*NDIM*NDIM];      // transposed fp16 weights

// ---------------------------------------------------------------------------
// PTX helpers (sm_80-era only)
// ---------------------------------------------------------------------------
static __device__ __forceinline__ uint32_t smem_u32(const void* p) {
    uint32_t a;
    asm("{ .reg .u64 t; cvta.to.shared.u64 t, %1; cvt.u32.u64 %0, t; }" : "=r"(a) : "l"(p));
    return a;
}
static __device__ __forceinline__ void cp16(uint32_t dst, const void* src) {
    asm volatile("cp.async.cg.shared.global [%0], [%1], 16;" :: "r"(dst), "l"(src));
}
#define CP_COMMIT() asm volatile("cp.async.commit_group;" ::: "memory")
#define CP_WAIT(n)  asm volatile("cp.async.wait_group %0;" :: "n"(n) : "memory")

#define LDSM4(r, addr) \
    asm volatile("ldmatrix.sync.aligned.m8n8.x4.shared.b16 {%0,%1,%2,%3}, [%4];" \
        : "=r"((r)[0]), "=r"((r)[1]), "=r"((r)[2]), "=r"((r)[3]) : "r"(addr))

static __device__ __forceinline__ void mma16816(float* c, const uint32_t* a,
                                                const uint32_t b0, const uint32_t b1) {
    asm volatile("mma.sync.aligned.m16n8k16.row.col.f32.f16.f16.f32 "
        "{%0,%1,%2,%3}, {%4,%5,%6,%7}, {%8,%9}, {%0,%1,%2,%3};"
        : "+f"(c[0]), "+f"(c[1]), "+f"(c[2]), "+f"(c[3])
        : "r"(a[0]), "r"(a[1]), "r"(a[2]), "r"(a[3]), "r"(b0), "r"(b1));
}

// fast tanh via MUFU: 1 - 2/(exp(2x)+1); saturates correctly at +-inf
static __device__ __forceinline__ float ftanh(float x) {
    float e, r;
    const float u = x * 2.8853900817779268f;   // 2*log2(e)
    asm("ex2.approx.f32 %0, %1;" : "=f"(e) : "f"(u));
    asm("rcp.approx.f32 %0, %1;" : "=f"(r) : "f"(e + 1.0f));
    return fmaf(-2.0f, r, 1.0f);
}

// ---------------------------------------------------------------------------
// Load one K-chunk: A 128x32 fp16 + B 128x32 fp16. 8 cp16/thread (128 thr).
// ---------------------------------------------------------------------------
static __device__ __forceinline__ void load_chunk(
    uint32_t stage,
    const __half* __restrict__ A, const __half* __restrict__ B,
    int m0, int n0, int kc0, int tid)
{
#pragma unroll
    for (int i = 0; i < 4; i++) {
        const int t   = tid + i * NTHR;      // 0..511
        const int row = t >> 2;              // 0..127
        const int q   = t & 3;
        const uint32_t so = (uint32_t)(row * ROWB + q * 16);
        cp16(stage + OFF_A + so, A + (size_t)(m0 + row) * NDIM + kc0 + q * 8);
        cp16(stage + OFF_B + so, B + (size_t)(n0 + row) * NDIM + kc0 + q * 8);
    }
    CP_COMMIT();
}

// ---------------------------------------------------------------------------
// fp16 GEMM: C[M,N] = act(A @ B^T + bias); CTA 128x128, 4 warps of 64x64
// 4-stage cp.async pipeline, one barrier per chunk, loads lead compute.
// EPI: 0 -> fp32 outF; 1 -> tanh fp16 outH; 2 -> relu fp16 outH;
//      3 -> final [m,n,4] {v, im, im, im}, im = noise*sin(alpha*n)
// ---------------------------------------------------------------------------
template<int EPI>
__global__ void __launch_bounds__(NTHR, 2)
gemm_f16(const __half* __restrict__ A, const __half* __restrict__ B,
         const float* __restrict__ bias,
         __half* __restrict__ outH, float* __restrict__ outF,
         const float* __restrict__ noise, const float* __restrict__ alpha_p)
{
    extern __shared__ char smem[];
    const uint32_t sb = smem_u32(smem);
    const int tid  = threadIdx.x;
    const int wid  = tid >> 5;
    const int lane = tid & 31;
    const int m0 = blockIdx.y * BM;
    const int n0 = blockIdx.x * BN;

    const int wm = wid & 1;        // 2 warps along M (64 rows each)
    const int wn = wid >> 1;       // 2 warps along N (64 cols each)

    float* bias_s = (float*)(smem + 64);     // 128 floats
    float* fm_s   = (float*)(smem + 576);    // 128 floats
    bias_s[tid] = bias[n0 + tid];
    if (EPI == 3) fm_s[tid] = sinf((*alpha_p) * (float)(n0 + tid));

    // prologue: 3 chunk-loads in flight
    load_chunk(sb + SM_CTRL + 0 * STAGE_BYTES, A, B, m0, n0, 0 * BK, tid);
    load_chunk(sb + SM_CTRL + 1 * STAGE_BYTES, A, B, m0, n0, 1 * BK, tid);
    load_chunk(sb + SM_CTRL + 2 * STAGE_BYTES, A, B, m0, n0, 2 * BK, tid);

    const int g  = lane >> 3;
    const int lr = lane & 7;
    const uint32_t offA = (uint32_t)((wm * 64 + (g & 1) * 8 + lr) * ROWB + (g >> 1) * 16);
    const uint32_t offB = (uint32_t)((wn * 64 + (g >> 1) * 8 + lr) * ROWB + (g & 1) * 16);

    float acc[4][8][4];
#pragma unroll
    for (int mt = 0; mt < 4; mt++)
#pragma unroll
        for (int nt = 0; nt < 8; nt++)
#pragma unroll
            for (int r = 0; r < 4; r++) acc[mt][nt][r] = 0.f;

#pragma unroll 1
    for (int c = 0; c < NCHUNK; c++) {
        CP_WAIT(2);                 // chunk c landed (c+1, c+2 may be pending)
        __syncthreads();            // also proves all warps finished chunk c-1

        // slot (c+3)&3 held chunk c-1 -> free now; refill it ahead of compute
        if (c + 3 < NCHUNK)
            load_chunk(sb + SM_CTRL + ((c + 3) & 3) * STAGE_BYTES,
                       A, B, m0, n0, (c + 3) * BK, tid);
        else
            CP_COMMIT();            // empty group keeps wait accounting exact

        const uint32_t stage = sb + SM_CTRL + (c & 3) * STAGE_BYTES;
#pragma unroll
        for (int ks = 0; ks < 2; ks++) {
            uint32_t a[4][4], b[4][4];
#pragma unroll
            for (int mt = 0; mt < 4; mt++)
                LDSM4(a[mt], stage + OFF_A + offA + mt * (16 * ROWB) + ks * 32);
#pragma unroll
            for (int bt = 0; bt < 4; bt++)
                LDSM4(b[bt], stage + OFF_B + offB + bt * (16 * ROWB) + ks * 32);
#pragma unroll
            for (int mt = 0; mt < 4; mt++)
#pragma unroll
                for (int nt = 0; nt < 8; nt++) {
                    const int bt = nt >> 1, sel = (nt & 1) * 2;
                    mma16816(acc[mt][nt], a[mt], b[bt][sel], b[bt][sel + 1]);
                }
        }
    }
    __syncthreads();   // stages dead; reuse smem for epilogue staging

    // ------------------------- epilogue -------------------------
    const int rbase = wm * 64 + (lane >> 2);
    const int cbase = wn * 64 + (lane & 3) * 2;

    if (EPI == 1 || EPI == 2) {
        __half* sH = (__half*)(smem + SM_CTRL);      // stride 136 halves (272B)
#pragma unroll
        for (int mt = 0; mt < 4; mt++)
#pragma unroll
            for (int nt = 0; nt < 8; nt++) {
                const int col = cbase + nt * 8;
#pragma unroll
                for (int h = 0; h < 2; h++) {
                    const int r = rbase + mt * 16 + h * 8;
                    float v0 = acc[mt][nt][h * 2 + 0] + bias_s[col + 0];
                    float v1 = acc[mt][nt][h * 2 + 1] + bias_s[col + 1];
                    if (EPI == 1) { v0 = ftanh(v0); v1 = ftanh(v1); }
                    else          { v0 = fmaxf(v0, 0.f); v1 = fmaxf(v1, 0.f); }
                    *(__half2*)&sH[r * 136 + col] = __floats2half2_rn(v0, v1);
                }
            }
        __syncthreads();
#pragma unroll
        for (int i = 0; i < 16; i++) {
            const int t = tid + i * NTHR;         // 0..2047
            const int row = t >> 4, q = t & 15;   // 16 uint4 per 256B row
            *(uint4*)((char*)outH + ((size_t)(m0 + row) * NDIM + n0) * 2 + q * 16) =
                *(uint4*)((char*)sH + row * 272 + q * 16);
        }
    } else {
        float* sC = (float*)(smem + SM_CTRL);     // stride 132 floats (528B)
#pragma unroll
        for (int mt = 0; mt < 4; mt++)
#pragma unroll
            for (int nt = 0; nt < 8; nt++) {
                const int col = cbase + nt * 8;
#pragma unroll
                for (int h = 0; h < 2; h++) {
                    const int r = rbase + mt * 16 + h * 8;
                    sC[r * 132 + col + 0] = acc[mt][nt][h * 2 + 0] + bias_s[col + 0];
                    sC[r * 132 + col + 1] = acc[mt][nt][h * 2 + 1] + bias_s[col + 1];
                }
            }
        __syncthreads();
        if (EPI == 0) {
#pragma unroll
            for (int i = 0; i < 32; i++) {
                const int t = tid + i * NTHR;     // 0..4095
                const int row = t >> 5, q = t & 31;
                *(float4*)(outF + (size_t)(m0 + row) * NDIM + n0 + q * 4) =
                    *(float4*)((char*)sC + row * 528 + q * 16);
            }
        } else {   // EPI == 3
#pragma unroll 4
            for (int i = 0; i < 128; i++) {
                const int t = tid + i * NTHR;     // 0..16383
                const int row = t >> 7, n = t & 127;
                const float v  = sC[row * 132 + n];
                const size_t e = (size_t)(m0 + row) * NDIM + n0 + n;
                const float im = noise[e] * fm_s[n];
                *(float4*)(outF + e * 4) = make_float4(v, im, im, im);
            }
        }
    }
}

// ---------------------------------------------------------------------------
// fp32 -> fp16 (for x)
// ---------------------------------------------------------------------------
__global__ void __launch_bounds__(256)
conv_f16(const float* __restrict__ x, __half* __restrict__ o)
{
    const int n4 = M_TOK * NDIM / 4;
    for (int i = blockIdx.x * blockDim.x + threadIdx.x; i < n4; i += gridDim.x * blockDim.x) {
        const float4 v = *(const float4*)(x + i * 4);
        __half2* O = (__half2*)(o + i * 4);
        O[0] = __floats2half2_rn(v.x, v.y);
        O[1] = __floats2half2_rn(v.z, v.w);
    }
}

// ---------------------------------------------------------------------------
// Weight prep (all 4 weights in one launch): Wt[n,k] = W[k,n] as fp16
// ---------------------------------------------------------------------------
__global__ void __launch_bounds__(256)
wprep4(const float* __restrict__ W1, const float* __restrict__ W2,
       const float* __restrict__ F1, const float* __restrict__ F2,
       __half* __restrict__ T)
{
    const float* W = (blockIdx.z == 0) ? W1 : (blockIdx.z == 1) ? W2
                   : (blockIdx.z == 2) ? F1 : F2;
    __half* Tz = T + (size_t)blockIdx.z * NDIM * NDIM;

    __shared__ float tile[32][33];
    const int bx = blockIdx.x * 32, by = blockIdx.y * 32;
    const int tx = threadIdx.x & 31, ty = threadIdx.x >> 5;  // 32 x 8
#pragma unroll
    for (int r = 0; r < 32; r += 8)
        tile[ty + r][tx] = W[(size_t)(by + ty + r) * NDIM + bx + tx];
    __syncthreads();
#pragma unroll
    for (int r = 0; r < 32; r += 8)
        Tz[(size_t)(bx + ty + r) * NDIM + by + tx] = __float2half_rn(tile[tx][ty + r]);
}

// ---------------------------------------------------------------------------
// Kuramoto: 10 steps (rotation trick), emits fp16 phases
// ---------------------------------------------------------------------------
__global__ void __launch_bounds__(256)
kuramoto_kernel(const float* __restrict__ P, const float* __restrict__ omega,
                const float* __restrict__ Kp, __half* __restrict__ outH)
{
    const int gwarp = (blockIdx.x * blockDim.x + threadIdx.x) >> 5;
    const int lane  = threadIdx.x & 31;
    if (gwarp >= M_TOK) return;

    const float* ph = P + (size_t)gwarp * NDIM;
    const float Kv = *Kp;
    const float a_scale = DT_C * Kv * (1.0f / (float)NDIM);

    float p[16], s[16], c[16], w[16];
#pragma unroll
    for (int i = 0; i < 16; i++) {
        const int e = lane + 32 * i;
        p[i] = ph[e];
        w[i] = DT_C * omega[e];
        __sincosf(p[i], &s[i], &c[i]);   // MUFU; |p| ~ O(3), err ~1e-6
    }
#pragma unroll 1
    for (int step = 0; step < NSTEPS; step++) {
        float part = 0.f;
#pragma unroll
        for (int i = 0; i < 16; i++) part += s[i];
#pragma unroll
        for (int off = 16; off > 0; off >>= 1)
            part += __shfl_xor_sync(0xFFFFFFFFu, part, off);
        const float a = a_scale * part;
#pragma unroll
        for (int i = 0; i < 16; i++) {
            const float d  = fmaf(a, c[i], w[i]);
            p[i] += d;
            const float cd = fmaf(-0.5f * d, d, 1.0f);
            const float sn = fmaf(c[i],  d, s[i] * cd);
            const float cn = fmaf(-s[i], d, c[i] * cd);
            s[i] = sn; c[i] = cn;
        }
    }
    const size_t base = (size_t)gwarp * NDIM;
#pragma unroll
    for (int i = 0; i < 16; i++)
        outH[base + lane + 32 * i] = __float2half_rn(p[i]);
}

// ---------------------------------------------------------------------------
extern "C" void kernel_launch(void* const* d_in, const int* in_sizes, int n_in,
                              void* d_out, int out_size)
{
    const float* x      = (const float*)d_in[0];
    const float* W1     = (const float*)d_in[1];
    const float* b1     = (const float*)d_in[2];
    const float* W2     = (const float*)d_in[3];
    const float* b2     = (const float*)d_in[4];
    const float* omega  = (const float*)d_in[5];
    const float* Kp     = (const float*)d_in[6];
    const float* alphap = (const float*)d_in[7];
    const float* F1     = (const float*)d_in[8];
    const float* c1     = (const float*)d_in[9];
    const float* F2     = (const float*)d_in[10];
    const float* c2     = (const float*)d_in[11];
    const float* noise  = (const float*)d_in[12];
    float* out = (float*)d_out;

    __half *actA, *actB, *wT;
    float* phb;
    cudaGetSymbolAddress((void**)&actA, g_act_a);
    cudaGetSymbolAddress((void**)&actB, g_act_b);
    cudaGetSymbolAddress((void**)&wT,   g_w);
    cudaGetSymbolAddress((void**)&phb,  g_ph);

    cudaFuncSetAttribute(gemm_f16<0>, cudaFuncAttributeMaxDynamicSharedMemorySize, GEMM_SMEM);
    cudaFuncSetAttribute(gemm_f16<1>, cudaFuncAttributeMaxDynamicSharedMemorySize, GEMM_SMEM);
    cudaFuncSetAttribute(gemm_f16<2>, cudaFuncAttributeMaxDynamicSharedMemorySize, GEMM_SMEM);
    cudaFuncSetAttribute(gemm_f16<3>, cudaFuncAttributeMaxDynamicSharedMemorySize, GEMM_SMEM);

    const size_t WSZ = (size_t)NDIM * NDIM;
    wprep4<<<dim3(16, 16, 4), 256>>>(W1, W2, F1, F2, wT);
    conv_f16<<<2048, 256>>>(x, actA);

    dim3 ggrid(NDIM / BN, M_TOK / BM);   // (4, 256) = 1024 CTAs

    // phases = tanh(x @ W1 + b1) -> fp16
    gemm_f16<1><<<ggrid, NTHR, GEMM_SMEM>>>(actA, wT + 0*WSZ,
                                            b1, actB, nullptr, nullptr, nullptr);
    // phases = phases @ W2 + b2 -> fp32
    gemm_f16<0><<<ggrid, NTHR, GEMM_SMEM>>>(actB, wT + 1*WSZ,
                                            b2, nullptr, phb, nullptr, nullptr);
    // Kuramoto -> fp16 phases
    kuramoto_kernel<<<M_TOK / 8, 256>>>(phb, omega, Kp, actA);
    // h = relu(phases @ F1 + c1) -> fp16
    gemm_f16<2><<<ggrid, NTHR, GEMM_SMEM>>>(actA, wT + 2*WSZ,
                                            c1, actB, nullptr, nullptr, nullptr);
    // out = expand(h @ F2 + c2, noise)
    gemm_f16<3><<<ggrid, NTHR, GEMM_SMEM>>>(actB, wT + 3*WSZ,
                                            c2, nullptr, out, noise, alphap);
}

// round 9
// speedup vs baseline: 4.8838x; 1.0571x over previous
#include <cuda_runtime.h>
#include <cuda_fp16.h>
#include <cstdint>
#include <math.h>

// ---------------------------------------------------------------------------
#define M_TOK 32768      // B*S
#define NDIM  512        // E = O
#define DT_C  0.01f
#define NSTEPS 10

#define BM 128
#define BN 128
#define BK 32
#define NCHUNK 16        // 512/32
#define NTHR 256         // 8 warps
#define NSTAGE 4

// smem: rows of 80B (64B data + 16B pad -> conflict-free ldmatrix)
#define ROWB 80
#define TILE_BYTES (128 * ROWB)            // 10240
#define OFF_A  0
#define OFF_B  TILE_BYTES
#define STAGE_BYTES (2 * TILE_BYTES)       // 20480 (A+B)
#define SM_CTRL 2560
// stage area 4*20480 = 81920; epilogue staging (128 x 132 fl = 67584) reuses it
#define GEMM_SMEM (SM_CTRL + NSTAGE * STAGE_BYTES)   // 84480; x2 CTAs = 169KB

// ---------------------------------------------------------------------------
// Global scratch (allocation-free rule)
// ---------------------------------------------------------------------------
__device__ __half g_act_a[M_TOK*NDIM];   // activations ping
__device__ __half g_act_b[M_TOK*NDIM];   // activations pong
__device__ float  g_ph[M_TOK*NDIM];      // fp32 phases for Kuramoto
__device__ __half g_w[4*NDIM*NDIM];      // transposed fp16 weights

// ---------------------------------------------------------------------------
// PTX helpers (sm_80-era only)
// ---------------------------------------------------------------------------
static __device__ __forceinline__ uint32_t smem_u32(const void* p) {
    uint32_t a;
    asm("{ .reg .u64 t; cvta.to.shared.u64 t, %1; cvt.u32.u64 %0, t; }" : "=r"(a) : "l"(p));
    return a;
}
static __device__ __forceinline__ void cp16(uint32_t dst, const void* src) {
    asm volatile("cp.async.cg.shared.global [%0], [%1], 16;" :: "r"(dst), "l"(src));
}
#define CP_COMMIT() asm volatile("cp.async.commit_group;" ::: "memory")
#define CP_WAIT(n)  asm volatile("cp.async.wait_group %0;" :: "n"(n) : "memory")

#define LDSM4(r, addr) \
    asm volatile("ldmatrix.sync.aligned.m8n8.x4.shared.b16 {%0,%1,%2,%3}, [%4];" \
        : "=r"((r)[0]), "=r"((r)[1]), "=r"((r)[2]), "=r"((r)[3]) : "r"(addr))

static __device__ __forceinline__ void mma16816(float* c, const uint32_t* a,
                                                const uint32_t b0, const uint32_t b1) {
    asm volatile("mma.sync.aligned.m16n8k16.row.col.f32.f16.f16.f32 "
        "{%0,%1,%2,%3}, {%4,%5,%6,%7}, {%8,%9}, {%0,%1,%2,%3};"
        : "+f"(c[0]), "+f"(c[1]), "+f"(c[2]), "+f"(c[3])
        : "r"(a[0]), "r"(a[1]), "r"(a[2]), "r"(a[3]), "r"(b0), "r"(b1));
}

// fast tanh via MUFU: 1 - 2/(exp(2x)+1); saturates correctly at +-inf
static __device__ __forceinline__ float ftanh(float x) {
    float e, r;
    const float u = x * 2.8853900817779268f;   // 2*log2(e)
    asm("ex2.approx.f32 %0, %1;" : "=f"(e) : "f"(u));
    asm("rcp.approx.f32 %0, %1;" : "=f"(r) : "f"(e + 1.0f));
    return fmaf(-2.0f, r, 1.0f);
}

// ---------------------------------------------------------------------------
// Load one K-chunk: A 128x32 fp16 + B 128x32 fp16. 4 cp16/thread (256 thr).
// ---------------------------------------------------------------------------
static __device__ __forceinline__ void load_chunk(
    uint32_t stage,
    const __half* __restrict__ A, const __half* __restrict__ B,
    int m0, int n0, int kc0, int tid)
{
#pragma unroll
    for (int i = 0; i < 2; i++) {
        const int t   = tid + i * NTHR;      // 0..511
        const int row = t >> 2;              // 0..127
        const int q   = t & 3;
        const uint32_t so = (uint32_t)(row * ROWB + q * 16);
        cp16(stage + OFF_A + so, A + (size_t)(m0 + row) * NDIM + kc0 + q * 8);
        cp16(stage + OFF_B + so, B + (size_t)(n0 + row) * NDIM + kc0 + q * 8);
    }
    CP_COMMIT();
}

// ---------------------------------------------------------------------------
// fp16 GEMM: C[M,N] = act(A @ B^T + bias); CTA 128x128, 8 warps of 32x64
// 4-stage cp.async pipeline, one barrier per chunk, loads lead compute.
// EPI: 0 -> fp32 outF; 1 -> tanh fp16 outH; 2 -> relu fp16 outH;
//      3 -> final [m,n,4] {v, im, im, im}, im = noise*sin(alpha*n)
// ---------------------------------------------------------------------------
template<int EPI>
__global__ void __launch_bounds__(NTHR, 2)
gemm_f16(const __half* __restrict__ A, const __half* __restrict__ B,
         const float* __restrict__ bias,
         __half* __restrict__ outH, float* __restrict__ outF,
         const float* __restrict__ noise, const float* __restrict__ alpha_p)
{
    extern __shared__ char smem[];
    const uint32_t sb = smem_u32(smem);
    const int tid  = threadIdx.x;
    const int wid  = tid >> 5;
    const int lane = tid & 31;
    const int m0 = blockIdx.y * BM;
    const int n0 = blockIdx.x * BN;

    const int wm = wid & 3;        // 4 warps along M (32 rows each)
    const int wn = wid >> 2;       // 2 warps along N (64 cols each)

    float* bias_s = (float*)(smem + 64);     // 128 floats
    float* fm_s   = (float*)(smem + 576);    // 128 floats
    if (tid < 128) {
        bias_s[tid] = bias[n0 + tid];
        if (EPI == 3) fm_s[tid] = sinf((*alpha_p) * (float)(n0 + tid));
    }

    // prologue: 3 chunk-loads in flight
    load_chunk(sb + SM_CTRL + 0 * STAGE_BYTES, A, B, m0, n0, 0 * BK, tid);
    load_chunk(sb + SM_CTRL + 1 * STAGE_BYTES, A, B, m0, n0, 1 * BK, tid);
    load_chunk(sb + SM_CTRL + 2 * STAGE_BYTES, A, B, m0, n0, 2 * BK, tid);

    const int g  = lane >> 3;
    const int lr = lane & 7;
    const uint32_t offA = (uint32_t)((wm * 32 + (g & 1) * 8 + lr) * ROWB + (g >> 1) * 16);
    const uint32_t offB = (uint32_t)((wn * 64 + (g >> 1) * 8 + lr) * ROWB + (g & 1) * 16);

    float acc[2][8][4];
#pragma unroll
    for (int mt = 0; mt < 2; mt++)
#pragma unroll
        for (int nt = 0; nt < 8; nt++)
#pragma unroll
            for (int r = 0; r < 4; r++) acc[mt][nt][r] = 0.f;

#pragma unroll 1
    for (int c = 0; c < NCHUNK; c++) {
        CP_WAIT(2);                 // chunk c landed (c+1, c+2 may be pending)
        __syncthreads();            // also proves all warps finished chunk c-1

        // slot (c+3)&3 held chunk c-1 -> free now; refill ahead of compute
        if (c + 3 < NCHUNK)
            load_chunk(sb + SM_CTRL + ((c + 3) & 3) * STAGE_BYTES,
                       A, B, m0, n0, (c + 3) * BK, tid);
        else
            CP_COMMIT();            // empty group keeps wait accounting exact

        const uint32_t stage = sb + SM_CTRL + (c & 3) * STAGE_BYTES;
#pragma unroll
        for (int ks = 0; ks < 2; ks++) {
            uint32_t a[2][4], b[4][4];
#pragma unroll
            for (int mt = 0; mt < 2; mt++)
                LDSM4(a[mt], stage + OFF_A + offA + mt * (16 * ROWB) + ks * 32);
#pragma unroll
            for (int bt = 0; bt < 4; bt++)
                LDSM4(b[bt], stage + OFF_B + offB + bt * (16 * ROWB) + ks * 32);
#pragma unroll
            for (int mt = 0; mt < 2; mt++)
#pragma unroll
                for (int nt = 0; nt < 8; nt++) {
                    const int bt = nt >> 1, sel = (nt & 1) * 2;
                    mma16816(acc[mt][nt], a[mt], b[bt][sel], b[bt][sel + 1]);
                }
        }
    }
    __syncthreads();   // stages dead; reuse smem for epilogue staging

    // ------------------------- epilogue -------------------------
    const int rbase = wm * 32 + (lane >> 2);
    const int cbase = wn * 64 + (lane & 3) * 2;

    if (EPI == 1 || EPI == 2) {
        __half* sH = (__half*)(smem + SM_CTRL);      // stride 136 halves (272B)
#pragma unroll
        for (int mt = 0; mt < 2; mt++)
#pragma unroll
            for (int nt = 0; nt < 8; nt++) {
                const int col = cbase + nt * 8;
#pragma unroll
                for (int h = 0; h < 2; h++) {
                    const int r = rbase + mt * 16 + h * 8;
                    float v0 = acc[mt][nt][h * 2 + 0] + bias_s[col + 0];
                    float v1 = acc[mt][nt][h * 2 + 1] + bias_s[col + 1];
                    if (EPI == 1) { v0 = ftanh(v0); v1 = ftanh(v1); }
                    else          { v0 = fmaxf(v0, 0.f); v1 = fmaxf(v1, 0.f); }
                    *(__half2*)&sH[r * 136 + col] = __floats2half2_rn(v0, v1);
                }
            }
        __syncthreads();
#pragma unroll
        for (int i = 0; i < 8; i++) {
            const int t = tid + i * NTHR;         // 0..2047
            const int row = t >> 4, q = t & 15;   // 16 uint4 per 256B row
            *(uint4*)((char*)outH + ((size_t)(m0 + row) * NDIM + n0) * 2 + q * 16) =
                *(uint4*)((char*)sH + row * 272 + q * 16);
        }
    } else {
        float* sC = (float*)(smem + SM_CTRL);     // stride 132 floats (528B)
#pragma unroll
        for (int mt = 0; mt < 2; mt++)
#pragma unroll
            for (int nt = 0; nt < 8; nt++) {
                const int col = cbase + nt * 8;
#pragma unroll
                for (int h = 0; h < 2; h++) {
                    const int r = rbase + mt * 16 + h * 8;
                    sC[r * 132 + col + 0] = acc[mt][nt][h * 2 + 0] + bias_s[col + 0];
                    sC[r * 132 + col + 1] = acc[mt][nt][h * 2 + 1] + bias_s[col + 1];
                }
            }
        __syncthreads();
        if (EPI == 0) {
#pragma unroll
            for (int i = 0; i < 16; i++) {
                const int t = tid + i * NTHR;     // 0..4095
                const int row = t >> 5, q = t & 31;
                *(float4*)(outF + (size_t)(m0 + row) * NDIM + n0 + q * 4) =
                    *(float4*)((char*)sC + row * 528 + q * 16);
            }
        } else {   // EPI == 3
#pragma unroll 4
            for (int i = 0; i < 64; i++) {
                const int t = tid + i * NTHR;     // 0..16383
                const int row = t >> 7, n = t & 127;
                const float v  = sC[row * 132 + n];
                const size_t e = (size_t)(m0 + row) * NDIM + n0 + n;
                const float im = noise[e] * fm_s[n];
                *(float4*)(outF + e * 4) = make_float4(v, im, im, im);
            }
        }
    }
}

// ---------------------------------------------------------------------------
// fp32 -> fp16 (for x)
// ---------------------------------------------------------------------------
__global__ void __launch_bounds__(256)
conv_f16(const float* __restrict__ x, __half* __restrict__ o)
{
    const int n4 = M_TOK * NDIM / 4;
    for (int i = blockIdx.x * blockDim.x + threadIdx.x; i < n4; i += gridDim.x * blockDim.x) {
        const float4 v = *(const float4*)(x + i * 4);
        __half2* O = (__half2*)(o + i * 4);
        O[0] = __floats2half2_rn(v.x, v.y);
        O[1] = __floats2half2_rn(v.z, v.w);
    }
}

// ---------------------------------------------------------------------------
// Weight prep (all 4 weights in one launch): Wt[n,k] = W[k,n] as fp16
// ---------------------------------------------------------------------------
__global__ void __launch_bounds__(256)
wprep4(const float* __restrict__ W1, const float* __restrict__ W2,
       const float* __restrict__ F1, const float* __restrict__ F2,
       __half* __restrict__ T)
{
    const float* W = (blockIdx.z == 0) ? W1 : (blockIdx.z == 1) ? W2
                   : (blockIdx.z == 2) ? F1 : F2;
    __half* Tz = T + (size_t)blockIdx.z * NDIM * NDIM;

    __shared__ float tile[32][33];
    const int bx = blockIdx.x * 32, by = blockIdx.y * 32;
    const int tx = threadIdx.x & 31, ty = threadIdx.x >> 5;  // 32 x 8
#pragma unroll
    for (int r = 0; r < 32; r += 8)
        tile[ty + r][tx] = W[(size_t)(by + ty + r) * NDIM + bx + tx];
    __syncthreads();
#pragma unroll
    for (int r = 0; r < 32; r += 8)
        Tz[(size_t)(bx + ty + r) * NDIM + by + tx] = __float2half_rn(tile[tx][ty + r]);
}

// ---------------------------------------------------------------------------
// Kuramoto: 10 steps (rotation trick), emits fp16 phases
// ---------------------------------------------------------------------------
__global__ void __launch_bounds__(256)
kuramoto_kernel(const float* __restrict__ P, const float* __restrict__ omega,
                const float* __restrict__ Kp, __half* __restrict__ outH)
{
    const int gwarp = (blockIdx.x * blockDim.x + threadIdx.x) >> 5;
    const int lane  = threadIdx.x & 31;
    if (gwarp >= M_TOK) return;

    const float* ph = P + (size_t)gwarp * NDIM;
    const float Kv = *Kp;
    const float a_scale = DT_C * Kv * (1.0f / (float)NDIM);

    float p[16], s[16], c[16], w[16];
#pragma unroll
    for (int i = 0; i < 16; i++) {
        const int e = lane + 32 * i;
        p[i] = ph[e];
        w[i] = DT_C * omega[e];
        __sincosf(p[i], &s[i], &c[i]);   // MUFU; |p| ~ O(3), err ~1e-6
    }
#pragma unroll 1
    for (int step = 0; step < NSTEPS; step++) {
        float part = 0.f;
#pragma unroll
        for (int i = 0; i < 16; i++) part += s[i];
#pragma unroll
        for (int off = 16; off > 0; off >>= 1)
            part += __shfl_xor_sync(0xFFFFFFFFu, part, off);
        const float a = a_scale * part;
#pragma unroll
        for (int i = 0; i < 16; i++) {
            const float d  = fmaf(a, c[i], w[i]);
            p[i] += d;
            const float cd = fmaf(-0.5f * d, d, 1.0f);
            const float sn = fmaf(c[i],  d, s[i] * cd);
            const float cn = fmaf(-s[i], d, c[i] * cd);
            s[i] = sn; c[i] = cn;
        }
    }
    const size_t base = (size_t)gwarp * NDIM;
#pragma unroll
    for (int i = 0; i < 16; i++)
        outH[base + lane + 32 * i] = __float2half_rn(p[i]);
}

// ---------------------------------------------------------------------------
extern "C" void kernel_launch(void* const* d_in, const int* in_sizes, int n_in,
                              void* d_out, int out_size)
{
    const float* x      = (const float*)d_in[0];
    const float* W1     = (const float*)d_in[1];
    const float* b1     = (const float*)d_in[2];
    const float* W2     = (const float*)d_in[3];
    const float* b2     = (const float*)d_in[4];
    const float* omega  = (const float*)d_in[5];
    const float* Kp     = (const float*)d_in[6];
    const float* alphap = (const float*)d_in[7];
    const float* F1     = (const float*)d_in[8];
    const float* c1     = (const float*)d_in[9];
    const float* F2     = (const float*)d_in[10];
    const float* c2     = (const float*)d_in[11];
    const float* noise  = (const float*)d_in[12];
    float* out = (float*)d_out;

    __half *actA, *actB, *wT;
    float* phb;
    cudaGetSymbolAddress((void**)&actA, g_act_a);
    cudaGetSymbolAddress((void**)&actB, g_act_b);
    cudaGetSymbolAddress((void**)&wT,   g_w);
    cudaGetSymbolAddress((void**)&phb,  g_ph);

    cudaFuncSetAttribute(gemm_f16<0>, cudaFuncAttributeMaxDynamicSharedMemorySize, GEMM_SMEM);
    cudaFuncSetAttribute(gemm_f16<1>, cudaFuncAttributeMaxDynamicSharedMemorySize, GEMM_SMEM);
    cudaFuncSetAttribute(gemm_f16<2>, cudaFuncAttributeMaxDynamicSharedMemorySize, GEMM_SMEM);
    cudaFuncSetAttribute(gemm_f16<3>, cudaFuncAttributeMaxDynamicSharedMemorySize, GEMM_SMEM);

    const size_t WSZ = (size_t)NDIM * NDIM;
    wprep4<<<dim3(16, 16, 4), 256>>>(W1, W2, F1, F2, wT);
    conv_f16<<<2048, 256>>>(x, actA);

    dim3 ggrid(NDIM / BN, M_TOK / BM);   // (4, 256) = 1024 CTAs

    // phases = tanh(x @ W1 + b1) -> fp16
    gemm_f16<1><<<ggrid, NTHR, GEMM_SMEM>>>(actA, wT + 0*WSZ,
                                            b1, actB, nullptr, nullptr, nullptr);
    // phases = phases @ W2 + b2 -> fp32
    gemm_f16<0><<<ggrid, NTHR, GEMM_SMEM>>>(actB, wT + 1*WSZ,
                                            b2, nullptr, phb, nullptr, nullptr);
    // Kuramoto -> fp16 phases
    kuramoto_kernel<<<M_TOK / 8, 256>>>(phb, omega, Kp, actA);
    // h = relu(phases @ F1 + c1) -> fp16
    gemm_f16<2><<<ggrid, NTHR, GEMM_SMEM>>>(actA, wT + 2*WSZ,
                                            c1, actB, nullptr, nullptr, nullptr);
    // out = expand(h @ F2 + c2, noise)
    gemm_f16<3><<<ggrid, NTHR, GEMM_SMEM>>>(actB, wT + 3*WSZ,
                                            c2, nullptr, out, noise, alphap);
}

// round 10
// speedup vs baseline: 5.0434x; 1.0327x over previous
#include <cuda_runtime.h>
#include <cuda_fp16.h>
#include <cstdint>
#include <math.h>

// ---------------------------------------------------------------------------
#define M_TOK 32768      // B*S
#define NDIM  512        // E = O
#define DT_C  0.01f
#define NSTEPS 10

#define BM 128
#define BN 128
#define BK 32
#define NCHUNK 16        // 512/32
#define NTHR 128         // 4 warps, warp tile 64x64 (measured-best config)
#define NSTAGE 4
#define NTILES_N (NDIM / BN)            // 4
#define NTILES   ((M_TOK / BM) * NTILES_N)  // 1024
#define NPERS 304                        // 152 SMs x 2 resident CTAs

// smem: rows of 80B (64B data + 16B pad -> conflict-free ldmatrix)
#define ROWB 80
#define TILE_BYTES (128 * ROWB)            // 10240
#define OFF_A  0
#define OFF_B  TILE_BYTES
#define STAGE_BYTES (2 * TILE_BYTES)       // 20480 (A+B)
#define SM_CTRL 4608                       // 64 + bias[512] + fm[512]
#define GEMM_SMEM (SM_CTRL + NSTAGE * STAGE_BYTES)   // 86528; x2 CTAs = 173KB

// ---------------------------------------------------------------------------
// Global scratch (allocation-free rule)
// ---------------------------------------------------------------------------
__device__ __half g_act_a[M_TOK*NDIM];   // activations ping
__device__ __half g_act_b[M_TOK*NDIM];   // activations pong
__device__ float  g_ph[M_TOK*NDIM];      // fp32 phases for Kuramoto
__device__ __half g_w[4*NDIM*NDIM];      // transposed fp16 weights

// ---------------------------------------------------------------------------
// PTX helpers (sm_80-era only)
// ---------------------------------------------------------------------------
static __device__ __forceinline__ uint32_t smem_u32(const void* p) {
    uint32_t a;
    asm("{ .reg .u64 t; cvta.to.shared.u64 t, %1; cvt.u32.u64 %0, t; }" : "=r"(a) : "l"(p));
    return a;
}
static __device__ __forceinline__ void cp16(uint32_t dst, const void* src) {
    asm volatile("cp.async.cg.shared.global [%0], [%1], 16;" :: "r"(dst), "l"(src));
}
#define CP_COMMIT() asm volatile("cp.async.commit_group;" ::: "memory")
#define CP_WAIT(n)  asm volatile("cp.async.wait_group %0;" :: "n"(n) : "memory")

#define LDSM4(r, addr) \
    asm volatile("ldmatrix.sync.aligned.m8n8.x4.shared.b16 {%0,%1,%2,%3}, [%4];" \
        : "=r"((r)[0]), "=r"((r)[1]), "=r"((r)[2]), "=r"((r)[3]) : "r"(addr))

static __device__ __forceinline__ void mma16816(float* c, const uint32_t* a,
                                                const uint32_t b0, const uint32_t b1) {
    asm volatile("mma.sync.aligned.m16n8k16.row.col.f32.f16.f16.f32 "
        "{%0,%1,%2,%3}, {%4,%5,%6,%7}, {%8,%9}, {%0,%1,%2,%3};"
        : "+f"(c[0]), "+f"(c[1]), "+f"(c[2]), "+f"(c[3])
        : "r"(a[0]), "r"(a[1]), "r"(a[2]), "r"(a[3]), "r"(b0), "r"(b1));
}

// fast tanh via MUFU: 1 - 2/(exp(2x)+1); saturates correctly at +-inf
static __device__ __forceinline__ float ftanh(float x) {
    float e, r;
    const float u = x * 2.8853900817779268f;   // 2*log2(e)
    asm("ex2.approx.f32 %0, %1;" : "=f"(e) : "f"(u));
    asm("rcp.approx.f32 %0, %1;" : "=f"(r) : "f"(e + 1.0f));
    return fmaf(-2.0f, r, 1.0f);
}

// ---------------------------------------------------------------------------
// Load one K-chunk: A 128x32 fp16 + B 128x32 fp16. 8 cp16/thread (128 thr).
// ---------------------------------------------------------------------------
static __device__ __forceinline__ void load_chunk(
    uint32_t stage,
    const __half* __restrict__ A, const __half* __restrict__ B,
    int m0, int n0, int kc0, int tid)
{
#pragma unroll
    for (int i = 0; i < 4; i++) {
        const int t   = tid + i * NTHR;      // 0..511
        const int row = t >> 2;              // 0..127
        const int q   = t & 3;
        const uint32_t so = (uint32_t)(row * ROWB + q * 16);
        cp16(stage + OFF_A + so, A + (size_t)(m0 + row) * NDIM + kc0 + q * 8);
        cp16(stage + OFF_B + so, B + (size_t)(n0 + row) * NDIM + kc0 + q * 8);
    }
    CP_COMMIT();
}

// ---------------------------------------------------------------------------
// Persistent fp16 GEMM: C[M,N] = act(A @ B^T + bias)
// CTA 128x128, 4 warps of 64x64, 4-stage cp.async ring continuous across tiles.
// Epilogue writes straight from registers (no smem staging).
// EPI: 0 -> fp32 outF; 1 -> tanh fp16 outH; 2 -> relu fp16 outH;
//      3 -> final [m,n,4] {v, im, im, im}, im = noise*sin(alpha*n)
// ---------------------------------------------------------------------------
template<int EPI>
__global__ void __launch_bounds__(NTHR, 2)
gemm_f16(const __half* __restrict__ A, const __half* __restrict__ B,
         const float* __restrict__ bias,
         __half* __restrict__ outH, float* __restrict__ outF,
         const float* __restrict__ noise, const float* __restrict__ alpha_p)
{
    extern __shared__ char smem[];
    const uint32_t sb = smem_u32(smem);
    const int tid  = threadIdx.x;
    const int wid  = tid >> 5;
    const int lane = tid & 31;

    const int wm = wid & 1;        // 2 warps along M (64 rows each)
    const int wn = wid >> 1;       // 2 warps along N (64 cols each)

    // full-width bias / fractal tables (tile-invariant)
    float* bias_s = (float*)(smem + 64);      // 512 floats
    float* fm_s   = (float*)(smem + 2112);    // 512 floats
    {
        const float alpha = (EPI == 3) ? *alpha_p : 0.f;
#pragma unroll
        for (int i = tid; i < NDIM; i += NTHR) {
            bias_s[i] = bias[i];
            if (EPI == 3) fm_s[i] = sinf(alpha * (float)i);
        }
    }

    int t  = blockIdx.x;
    int m0 = (t >> 2) * BM;
    int n0 = (t & 3) * BN;

    // prologue: 3 chunk-loads of first tile in flight
    load_chunk(sb + SM_CTRL + 0 * STAGE_BYTES, A, B, m0, n0, 0 * BK, tid);
    load_chunk(sb + SM_CTRL + 1 * STAGE_BYTES, A, B, m0, n0, 1 * BK, tid);
    load_chunk(sb + SM_CTRL + 2 * STAGE_BYTES, A, B, m0, n0, 2 * BK, tid);

    const int g  = lane >> 3;
    const int lr = lane & 7;
    const uint32_t offA = (uint32_t)((wm * 64 + (g & 1) * 8 + lr) * ROWB + (g >> 1) * 16);
    const uint32_t offB = (uint32_t)((wn * 64 + (g >> 1) * 8 + lr) * ROWB + (g & 1) * 16);

    while (true) {
        const int tn  = t + NPERS;
        const bool has_next = (tn < NTILES);
        const int m0n = (tn >> 2) * BM;
        const int n0n = (tn & 3) * BN;

        float acc[4][8][4];
#pragma unroll
        for (int mt = 0; mt < 4; mt++)
#pragma unroll
            for (int nt = 0; nt < 8; nt++)
#pragma unroll
                for (int r = 0; r < 4; r++) acc[mt][nt][r] = 0.f;

#pragma unroll 1
        for (int c = 0; c < NCHUNK; c++) {
            CP_WAIT(2);             // chunk c landed (c+1, c+2 pending)
            __syncthreads();        // all warps done with chunk c-1

            const int cc = c + 3;   // refill the slot chunk c-1 vacated
            if (cc < NCHUNK)
                load_chunk(sb + SM_CTRL + (cc & 3) * STAGE_BYTES,
                           A, B, m0, n0, cc * BK, tid);
            else if (has_next)
                load_chunk(sb + SM_CTRL + (cc & 3) * STAGE_BYTES,
                           A, B, m0n, n0n, (cc - NCHUNK) * BK, tid);
            else
                CP_COMMIT();        // empty group keeps accounting exact

            const uint32_t stage = sb + SM_CTRL + (c & 3) * STAGE_BYTES;
#pragma unroll
            for (int ks = 0; ks < 2; ks++) {
                uint32_t a[4][4], b[4][4];
#pragma unroll
                for (int mt = 0; mt < 4; mt++)
                    LDSM4(a[mt], stage + OFF_A + offA + mt * (16 * ROWB) + ks * 32);
#pragma unroll
                for (int bt = 0; bt < 4; bt++)
                    LDSM4(b[bt], stage + OFF_B + offB + bt * (16 * ROWB) + ks * 32);
#pragma unroll
                for (int mt = 0; mt < 4; mt++)
#pragma unroll
                    for (int nt = 0; nt < 8; nt++) {
                        const int bt = nt >> 1, sel = (nt & 1) * 2;
                        mma16816(acc[mt][nt], a[mt], b[bt][sel], b[bt][sel + 1]);
                    }
            }
        }

        // ---- epilogue: direct register -> global (overlaps next tile's loads)
        const int rbase = m0 + wm * 64 + (lane >> 2);
        const int cbase = n0 + wn * 64 + (lane & 3) * 2;
#pragma unroll
        for (int mt = 0; mt < 4; mt++)
#pragma unroll
            for (int nt = 0; nt < 8; nt++) {
                const int col = cbase + nt * 8;
#pragma unroll
                for (int h = 0; h < 2; h++) {
                    const int row = rbase + mt * 16 + h * 8;
                    float v0 = acc[mt][nt][h * 2 + 0] + bias_s[col + 0];
                    float v1 = acc[mt][nt][h * 2 + 1] + bias_s[col + 1];
                    const size_t e = (size_t)row * NDIM + col;
                    if (EPI == 1) {
                        *(__half2*)(outH + e) = __floats2half2_rn(ftanh(v0), ftanh(v1));
                    } else if (EPI == 2) {
                        *(__half2*)(outH + e) =
                            __floats2half2_rn(fmaxf(v0, 0.f), fmaxf(v1, 0.f));
                    } else if (EPI == 0) {
                        *(float2*)(outF + e) = make_float2(v0, v1);
                    } else {
                        const float2 nz = *(const float2*)(noise + e);
                        const float im0 = nz.x * fm_s[col + 0];
                        const float im1 = nz.y * fm_s[col + 1];
                        *(float4*)(outF + e * 4)       = make_float4(v0, im0, im0, im0);
                        *(float4*)(outF + (e + 1) * 4) = make_float4(v1, im1, im1, im1);
                    }
                }
            }

        if (!has_next) break;
        t = tn; m0 = m0n; n0 = n0n;
    }
}

// ---------------------------------------------------------------------------
// fp32 -> fp16 (for x)
// ---------------------------------------------------------------------------
__global__ void __launch_bounds__(256)
conv_f16(const float* __restrict__ x, __half* __restrict__ o)
{
    const int n4 = M_TOK * NDIM / 4;
    for (int i = blockIdx.x * blockDim.x + threadIdx.x; i < n4; i += gridDim.x * blockDim.x) {
        const float4 v = *(const float4*)(x + i * 4);
        __half2* O = (__half2*)(o + i * 4);
        O[0] = __floats2half2_rn(v.x, v.y);
        O[1] = __floats2half2_rn(v.z, v.w);
    }
}

// ---------------------------------------------------------------------------
// Weight prep (all 4 weights in one launch): Wt[n,k] = W[k,n] as fp16
// ---------------------------------------------------------------------------
__global__ void __launch_bounds__(256)
wprep4(const float* __restrict__ W1, const float* __restrict__ W2,
       const float* __restrict__ F1, const float* __restrict__ F2,
       __half* __restrict__ T)
{
    const float* W = (blockIdx.z == 0) ? W1 : (blockIdx.z == 1) ? W2
                   : (blockIdx.z == 2) ? F1 : F2;
    __half* Tz = T + (size_t)blockIdx.z * NDIM * NDIM;

    __shared__ float tile[32][33];
    const int bx = blockIdx.x * 32, by = blockIdx.y * 32;
    const int tx = threadIdx.x & 31, ty = threadIdx.x >> 5;  // 32 x 8
#pragma unroll
    for (int r = 0; r < 32; r += 8)
        tile[ty + r][tx] = W[(size_t)(by + ty + r) * NDIM + bx + tx];
    __syncthreads();
#pragma unroll
    for (int r = 0; r < 32; r += 8)
        Tz[(size_t)(bx + ty + r) * NDIM + by + tx] = __float2half_rn(tile[tx][ty + r]);
}

// ---------------------------------------------------------------------------
// Kuramoto: 10 steps (rotation trick), emits fp16 phases
// ---------------------------------------------------------------------------
__global__ void __launch_bounds__(256)
kuramoto_kernel(const float* __restrict__ P, const float* __restrict__ omega,
                const float* __restrict__ Kp, __half* __restrict__ outH)
{
    const int gwarp = (blockIdx.x * blockDim.x + threadIdx.x) >> 5;
    const int lane  = threadIdx.x & 31;
    if (gwarp >= M_TOK) return;

    const float* ph = P + (size_t)gwarp * NDIM;
    const float Kv = *Kp;
    const float a_scale = DT_C * Kv * (1.0f / (float)NDIM);

    float p[16], s[16], c[16], w[16];
#pragma unroll
    for (int i = 0; i < 16; i++) {
        const int e = lane + 32 * i;
        p[i] = ph[e];
        w[i] = DT_C * omega[e];
        __sincosf(p[i], &s[i], &c[i]);   // MUFU; |p| ~ O(3), err ~1e-6
    }
#pragma unroll 1
    for (int step = 0; step < NSTEPS; step++) {
        float part = 0.f;
#pragma unroll
        for (int i = 0; i < 16; i++) part += s[i];
#pragma unroll
        for (int off = 16; off > 0; off >>= 1)
            part += __shfl_xor_sync(0xFFFFFFFFu, part, off);
        const float a = a_scale * part;
#pragma unroll
        for (int i = 0; i < 16; i++) {
            const float d  = fmaf(a, c[i], w[i]);
            p[i] += d;
            const float cd = fmaf(-0.5f * d, d, 1.0f);
            const float sn = fmaf(c[i],  d, s[i] * cd);
            const float cn = fmaf(-s[i], d, c[i] * cd);
            s[i] = sn; c[i] = cn;
        }
    }
    const size_t base = (size_t)gwarp * NDIM;
#pragma unroll
    for (int i = 0; i < 16; i++)
        outH[base + lane + 32 * i] = __float2half_rn(p[i]);
}

// ---------------------------------------------------------------------------
extern "C" void kernel_launch(void* const* d_in, const int* in_sizes, int n_in,
                              void* d_out, int out_size)
{
    const float* x      = (const float*)d_in[0];
    const float* W1     = (const float*)d_in[1];
    const float* b1     = (const float*)d_in[2];
    const float* W2     = (const float*)d_in[3];
    const float* b2     = (const float*)d_in[4];
    const float* omega  = (const float*)d_in[5];
    const float* Kp     = (const float*)d_in[6];
    const float* alphap = (const float*)d_in[7];
    const float* F1     = (const float*)d_in[8];
    const float* c1     = (const float*)d_in[9];
    const float* F2     = (const float*)d_in[10];
    const float* c2     = (const float*)d_in[11];
    const float* noise  = (const float*)d_in[12];
    float* out = (float*)d_out;

    __half *actA, *actB, *wT;
    float* phb;
    cudaGetSymbolAddress((void**)&actA, g_act_a);
    cudaGetSymbolAddress((void**)&actB, g_act_b);
    cudaGetSymbolAddress((void**)&wT,   g_w);
    cudaGetSymbolAddress((void**)&phb,  g_ph);

    cudaFuncSetAttribute(gemm_f16<0>, cudaFuncAttributeMaxDynamicSharedMemorySize, GEMM_SMEM);
    cudaFuncSetAttribute(gemm_f16<1>, cudaFuncAttributeMaxDynamicSharedMemorySize, GEMM_SMEM);
    cudaFuncSetAttribute(gemm_f16<2>, cudaFuncAttributeMaxDynamicSharedMemorySize, GEMM_SMEM);
    cudaFuncSetAttribute(gemm_f16<3>, cudaFuncAttributeMaxDynamicSharedMemorySize, GEMM_SMEM);

    const size_t WSZ = (size_t)NDIM * NDIM;
    wprep4<<<dim3(16, 16, 4), 256>>>(W1, W2, F1, F2, wT);
    conv_f16<<<2048, 256>>>(x, actA);

    // phases = tanh(x @ W1 + b1) -> fp16
    gemm_f16<1><<<NPERS, NTHR, GEMM_SMEM>>>(actA, wT + 0*WSZ,
                                            b1, actB, nullptr, nullptr, nullptr);
    // phases = phases @ W2 + b2 -> fp32
    gemm_f16<0><<<NPERS, NTHR, GEMM_SMEM>>>(actB, wT + 1*WSZ,
                                            b2, nullptr, phb, nullptr, nullptr);
    // Kuramoto -> fp16 phases
    kuramoto_kernel<<<M_TOK / 8, 256>>>(phb, omega, Kp, actA);
    // h = relu(phases @ F1 + c1) -> fp16
    gemm_f16<2><<<NPERS, NTHR, GEMM_SMEM>>>(actA, wT + 2*WSZ,
                                            c1, actB, nullptr, nullptr, nullptr);
    // out = expand(h @ F2 + c2, noise)
    gemm_f16<3><<<NPERS, NTHR, GEMM_SMEM>>>(actB, wT + 3*WSZ,
                                            c2, nullptr, out, noise, alphap);
}